// round 11
// baseline (speedup 1.0000x reference)
#include <cuda_runtime.h>
#include <cuda_fp16.h>
#include <cstdint>
#include <cstddef>

#define NN 50000
#define EE 800000

// ---------------- scratch (device globals: allocation-free) ----------------
__device__ __align__(256) __half g_ac1[(size_t)NN * 2048]; // [hi|lo] ping
__device__ __align__(256) __half g_ac2[(size_t)NN * 2048]; // [hi|lo] pong
__device__ __align__(256) float g_t  [(size_t)NN * 80];    // feat + agg
__device__ __align__(256) float g_deg[NN];
__device__ __align__(256) __half g_wc[8454144];            // weight convs

// ---------------- warp-MMA helpers (baseline sm_80+ PTX only) --------------
__device__ __forceinline__ void ldsm4(uint32_t* r, uint32_t addr) {
    asm volatile("ldmatrix.sync.aligned.m8n8.x4.shared.b16 {%0,%1,%2,%3}, [%4];"
                 : "=r"(r[0]), "=r"(r[1]), "=r"(r[2]), "=r"(r[3]) : "r"(addr));
}
__device__ __forceinline__ void mma_fp16(float* c, const uint32_t* a,
                                         uint32_t b0, uint32_t b1) {
    asm volatile(
        "mma.sync.aligned.m16n8k16.row.col.f32.f16.f16.f32 "
        "{%0,%1,%2,%3}, {%4,%5,%6,%7}, {%8,%9}, {%0,%1,%2,%3};"
        : "+f"(c[0]), "+f"(c[1]), "+f"(c[2]), "+f"(c[3])
        : "r"(a[0]), "r"(a[1]), "r"(a[2]), "r"(a[3]), "r"(b0), "r"(b1));
}

// ---------------- fp16 tensor-core GEMM -------------------------------------
// A: [M, 2*Kp] fp16 [Ahi|Alo].  Bw: [Np, 3*Kp] fp16 [Whi|Whi|Wlo] (transposed).
// SEC=2: K' = 2*Kp -> Ahi.Whi + Alo.Whi     (weights fp16-quantized, ~2e-4)
// SEC=3: K' = 3*Kp -> + Ahi.Wlo             (near-fp32, ~1e-6)
// CTA tile 128x64, warp tile 32x32 (8 warps: 4 M-groups x 2 N-groups),
// BK=64, 2-stage cp.async pipeline, ~80 regs -> 3 CTA/SM (occ 37.5%).
// SMEM rows: 128B data @ 144B pitch (odd 16B granules -> conflict-free ldsm).
// Epilogue: X3 ? write [hi|lo] fp16 : write fp32. DEGFIX: +deg[r]*bias[c].
template <bool RELU, bool X3, bool DEGFIX, int SEC>
__global__ void __launch_bounds__(256, 3)
gemm_mma(const __half* __restrict__ A, const __half* __restrict__ Bw,
         const float* __restrict__ bias, float* __restrict__ Cf,
         __half* __restrict__ Cx, const float* __restrict__ deg,
         int M, int Nreal, int Kp)
{
    constexpr int PITCH  = 144;
    constexpr int ATILEB = 128 * PITCH;   // 18432
    constexpr int BTILEB = 64 * PITCH;    // 9216
    constexpr int STAGEB = ATILEB + BTILEB;

    extern __shared__ char smem[];
    const uint32_t sbase = (uint32_t)__cvta_generic_to_shared(smem);

    const int tid  = threadIdx.x;
    const int lane = tid & 31;
    const int wid  = tid >> 5;
    const int wm   = wid >> 1;            // 0..3  (M direction)
    const int wn   = wid & 1;             // 0..1  (N direction)
    const int block_row = blockIdx.y * 128;
    const int block_col = blockIdx.x * 64;

    const int KCH = Kp >> 6;              // hi-section chunks
    const int KT  = SEC * KCH;            // total weight chunks
    const int ldA = 2 * Kp * 2;           // A row stride bytes (2 sections)
    const int ldB = 3 * Kp * 2;           // W row stride bytes (3 sections)
    const char* Ag = (const char*)A + (size_t)block_row * ldA;
    const char* Bg = (const char*)Bw + (size_t)block_col * ldB;

    // A: row = tid/2, 4 chunks at (tid&1)*4.  B: row = tid/4, 2 chunks at (tid&3)*2.
    const int a_row = tid >> 1;
    const int a_c0  = (tid & 1) * 4;
    const int okA   = (block_row + a_row) < M ? 16 : 0;
    const char* ArowC = Ag + (size_t)((block_row + a_row) < M ? a_row : 0) * ldA;
    const int b_row = tid >> 2;
    const int b_c0  = (tid & 3) * 2;
    const char* BrowC = Bg + (size_t)b_row * ldB;

    auto load_stage = [&](int s, int kc) {
        int ka = (SEC == 3 && kc >= 2 * KCH) ? kc - 2 * KCH : kc;  // A map
        uint32_t abuf = sbase + s * STAGEB + a_row * PITCH;
        const char* Ak = ArowC + ka * 128;
#pragma unroll
        for (int it = 0; it < 4; it++) {
            int c = a_c0 + it;
            asm volatile("cp.async.cg.shared.global [%0], [%1], 16, %2;"
                         :: "r"(abuf + c * 16), "l"(Ak + c * 16), "r"(okA));
        }
        uint32_t bbuf = sbase + s * STAGEB + ATILEB + b_row * PITCH;
        const char* Bk = BrowC + kc * 128;
#pragma unroll
        for (int it = 0; it < 2; it++) {
            int c = b_c0 + it;
            asm volatile("cp.async.cg.shared.global [%0], [%1], 16;"
                         :: "r"(bbuf + c * 16), "l"(Bk + c * 16));
        }
    };

    float acc[2][4][4];
#pragma unroll
    for (int i = 0; i < 2; i++)
#pragma unroll
        for (int j = 0; j < 4; j++)
#pragma unroll
            for (int k = 0; k < 4; k++) acc[i][j][k] = 0.f;

    load_stage(0, 0);
    asm volatile("cp.async.commit_group;" ::: "memory");

    const uint32_t lrow = lane & 15;
    const uint32_t lhi  = (lane >> 4) << 4;
    uint32_t aoff[2], boff[2];
#pragma unroll
    for (int mt = 0; mt < 2; mt++)
        aoff[mt] = (wm * 32 + mt * 16 + lrow) * PITCH + lhi;
#pragma unroll
    for (int nt = 0; nt < 2; nt++)
        boff[nt] = ATILEB + (wn * 32 + nt * 16 + lrow) * PITCH + lhi;

    for (int ks = 0; ks < KT; ks++) {
        if (ks + 1 < KT) {
            load_stage((ks + 1) & 1, ks + 1);
            asm volatile("cp.async.commit_group;" ::: "memory");
            asm volatile("cp.async.wait_group 1;" ::: "memory");
        } else {
            asm volatile("cp.async.wait_group 0;" ::: "memory");
        }
        __syncthreads();

        uint32_t buf = sbase + (ks & 1) * STAGEB;
#pragma unroll
        for (int kk = 0; kk < 4; kk++) {          // four k16 steps per chunk
            uint32_t col = kk * 32;
            uint32_t afr[2][4];
#pragma unroll
            for (int mt = 0; mt < 2; mt++)
                ldsm4(afr[mt], buf + aoff[mt] + col);
            uint32_t bq[2][4];
#pragma unroll
            for (int nt = 0; nt < 2; nt++)
                ldsm4(bq[nt], buf + boff[nt] + col);
#pragma unroll
            for (int mt = 0; mt < 2; mt++)
#pragma unroll
                for (int n8 = 0; n8 < 4; n8++)
                    mma_fp16(acc[mt][n8], afr[mt],
                             bq[n8 >> 1][n8 & 1], bq[n8 >> 1][(n8 & 1) + 2]);
        }
        __syncthreads();                          // compute done before reuse
    }

    // epilogue
    const int g = lane >> 2, t = lane & 3;
    const size_t ldx = (size_t)2 * Nreal;     // [hi|lo] output layout
#pragma unroll
    for (int mt = 0; mt < 2; mt++) {
#pragma unroll
        for (int n8 = 0; n8 < 4; n8++) {
            int c = block_col + wn * 32 + n8 * 8 + t * 2;
            if (c >= Nreal) continue;
            float bx = __ldg(bias + c), by = __ldg(bias + c + 1);
#pragma unroll
            for (int h = 0; h < 2; h++) {
                int r = block_row + wm * 32 + mt * 16 + g + h * 8;
                if (r >= M) continue;
                float vx = acc[mt][n8][h * 2 + 0] + bx;
                float vy = acc[mt][n8][h * 2 + 1] + by;
                if (DEGFIX) {
                    float dg = __ldg(deg + r);
                    vx += dg * bx;
                    vy += dg * by;
                }
                if (RELU) { vx = fmaxf(vx, 0.f); vy = fmaxf(vy, 0.f); }
                if (X3) {
                    __half hx = __float2half_rn(vx);
                    __half hy = __float2half_rn(vy);
                    __half lx = __float2half_rn(vx - __half2float(hx));
                    __half ly = __float2half_rn(vy - __half2float(hy));
                    __half2 hi; hi.x = hx; hi.y = hy;
                    __half2 lo; lo.x = lx; lo.y = ly;
                    __half* p = Cx + (size_t)r * ldx + c;
                    *reinterpret_cast<__half2*>(p) = hi;
                    *reinterpret_cast<__half2*>(p + Nreal) = lo;
                } else {
                    float2 v; v.x = vx; v.y = vy;
                    *reinterpret_cast<float2*>(Cf + (size_t)r * Nreal + c) = v;
                }
            }
        }
    }
}

// ---------------- fp32 -> split-fp16 [hi | lo] conversion (float4) ----------
__global__ void conv_act(const float* __restrict__ in, __half* __restrict__ out,
                         int M, int K, int Kp)
{
    int q = Kp >> 2;
    int idx = blockIdx.x * blockDim.x + threadIdx.x;
    if (idx >= M * q) return;
    int r = idx / q;
    int k4 = (idx - r * q) * 4;
    float4 x = make_float4(0.f, 0.f, 0.f, 0.f);
    if (k4 < K)
        x = *reinterpret_cast<const float4*>(in + (size_t)r * K + k4);
    __half2 h0, h1, l0, l1;
    h0.x = __float2half_rn(x.x); h0.y = __float2half_rn(x.y);
    h1.x = __float2half_rn(x.z); h1.y = __float2half_rn(x.w);
    l0.x = __float2half_rn(x.x - __half2float(h0.x));
    l0.y = __float2half_rn(x.y - __half2float(h0.y));
    l1.x = __float2half_rn(x.z - __half2float(h1.x));
    l1.y = __float2half_rn(x.w - __half2float(h1.y));
    __half* b = out + (size_t)r * 2 * Kp;
    reinterpret_cast<__half2*>(b + k4)[0] = h0;
    reinterpret_cast<__half2*>(b + k4)[1] = h1;
    reinterpret_cast<__half2*>(b + Kp + k4)[0] = l0;
    reinterpret_cast<__half2*>(b + Kp + k4)[1] = l1;
}

// ---------------- all weight conversions in ONE kernel ----------------------
// W[K,N] fp32 -> [Np, 3*Kp] fp16, row n = [hi | hi | lo] (pairs with act [hi|lo])
struct WDesc { const float* W; __half* out; int K, N, Kp, Np; };
struct WAll  { WDesc d[8]; };

__global__ void conv_wt_all(WAll wa)
{
    WDesc d = wa.d[blockIdx.y];
    int tot = d.Np * d.Kp;
    for (int idx = blockIdx.x * blockDim.x + threadIdx.x; idx < tot;
         idx += gridDim.x * blockDim.x) {
        int n = idx / d.Kp;
        int k = idx - n * d.Kp;
        float x = (k < d.K && n < d.N) ? d.W[(size_t)k * d.N + n] : 0.f;
        __half hi = __float2half_rn(x);
        __half lo = __float2half_rn(x - __half2float(hi));
        size_t b = (size_t)n * 3 * d.Kp;
        d.out[b + k] = hi;
        d.out[b + d.Kp + k] = hi;
        d.out[b + 2 * d.Kp + k] = lo;
    }
}

// ---------------- GIN aggregation on 80-dim feat ----------------------------
__global__ void k_init_t(const float* __restrict__ feat, float* __restrict__ t,
                         float* __restrict__ deg, int n4, int N)
{
    int i = blockIdx.x * blockDim.x + threadIdx.x;
    if (i < n4)
        reinterpret_cast<float4*>(t)[i] = reinterpret_cast<const float4*>(feat)[i];
    if (i < N) deg[i] = 0.f;
}

__global__ void k_scatter(const float* __restrict__ feat, const int* __restrict__ ei,
                          float* __restrict__ t, float* __restrict__ deg, int E)
{
    int i = blockIdx.x * blockDim.x + threadIdx.x;
    if (i >= E * 20) return;
    int e = i / 20;
    int c = i - e * 20;
    int s = ei[e];
    int d = ei[E + e];
    float4 v = *reinterpret_cast<const float4*>(feat + (size_t)s * 80 + c * 4);
    float* p = t + (size_t)d * 80 + c * 4;
    asm volatile("red.global.add.v4.f32 [%0], {%1, %2, %3, %4};"
                 :: "l"(p), "f"(v.x), "f"(v.y), "f"(v.z), "f"(v.w) : "memory");
    if (c == 0) atomicAdd(deg + d, 1.f);
}

// ---------------- launch ----------------------------------------------------
static inline unsigned cdiv(long long a, long long b) { return (unsigned)((a + b - 1) / b); }

extern "C" void kernel_launch(void* const* d_in, const int* in_sizes, int n_in,
                              void* d_out, int out_size)
{
    const float* P    = (const float*)d_in[0];
    const int*   EI   = (const int*)  d_in[1];
    const float* W1   = (const float*)d_in[2];
    const float* b1   = (const float*)d_in[3];
    const float* W2   = (const float*)d_in[4];
    const float* b2   = (const float*)d_in[5];
    const float* W3   = (const float*)d_in[6];
    const float* b3   = (const float*)d_in[7];
    const float* W4   = (const float*)d_in[8];
    const float* b4   = (const float*)d_in[9];
    const float* Win  = (const float*)d_in[10];
    const float* bin_ = (const float*)d_in[11];
    const float* Wg1  = (const float*)d_in[12];
    const float* bg1  = (const float*)d_in[13];
    const float* Wg2  = (const float*)d_in[14];
    const float* bg2  = (const float*)d_in[15];
    const float* Wout = (const float*)d_in[16];
    const float* bout = (const float*)d_in[17];

    float* out  = (float*)d_out;
    float* mask = out;
    float* feat = out + (size_t)NN * 80;

    float *T, *DEG;
    __half *AC1, *AC2, *WC;
    cudaGetSymbolAddress((void**)&T,   g_t);
    cudaGetSymbolAddress((void**)&DEG, g_deg);
    cudaGetSymbolAddress((void**)&AC1, g_ac1);
    cudaGetSymbolAddress((void**)&AC2, g_ac2);
    cudaGetSymbolAddress((void**)&WC,  g_wc);

    // weight conv buffer offsets (elements)
    __half* W1c   = WC + 0;        // 1024 x 1536
    __half* W2c   = WC + 1572864;  // 1024 x 3072
    __half* W3c   = WC + 4718592;  // 512 x 3072
    __half* W4c   = WC + 6291456;  // 128 x 1536
    __half* Winc  = WC + 6488064;  // 512 x 384
    __half* Wg1c  = WC + 6684672;  // 512 x 1536
    __half* Wg2c  = WC + 7471104;  // 512 x 1536
    __half* Woutc = WC + 8257536;  // 128 x 1536

    const int M = NN;
    const int SMEM = 2 * (128 + 64) * 144;   // 55296 B -> 3 CTA/SM
    cudaFuncSetAttribute(gemm_mma<true,  true,  false, 2>, cudaFuncAttributeMaxDynamicSharedMemorySize, SMEM);
    cudaFuncSetAttribute(gemm_mma<false, false, false, 2>, cudaFuncAttributeMaxDynamicSharedMemorySize, SMEM);
    cudaFuncSetAttribute(gemm_mma<false, true,  false, 2>, cudaFuncAttributeMaxDynamicSharedMemorySize, SMEM);
    cudaFuncSetAttribute(gemm_mma<false, true,  true,  3>, cudaFuncAttributeMaxDynamicSharedMemorySize, SMEM);
    cudaFuncSetAttribute(gemm_mma<false, false, false, 3>, cudaFuncAttributeMaxDynamicSharedMemorySize, SMEM);

    const dim3 blk(256);
    const unsigned rt = cdiv(M, 128);

    // --- all weight conversions (one kernel) ---
    WAll wa;
    wa.d[0] = { W1,   W1c,    512, 1024,  512, 1024 };
    wa.d[1] = { W2,   W2c,   1024, 1024, 1024, 1024 };
    wa.d[2] = { W3,   W3c,   1024,  512, 1024,  512 };
    wa.d[3] = { W4,   W4c,    512,   80,  512,  128 };
    wa.d[4] = { Win,  Winc,    80,  512,  128,  512 };
    wa.d[5] = { Wg1,  Wg1c,   512,  512,  512,  512 };
    wa.d[6] = { Wg2,  Wg2c,   512,  512,  512,  512 };
    wa.d[7] = { Wout, Woutc,  512,   80,  512,  128 };
    conv_wt_all<<<dim3(2048, 8), blk>>>(wa);

    // --- expand P to [hi|lo] ---
    conv_act<<<cdiv((long long)M * 128, 256), blk>>>(P, AC1, M, 512, 512);

    // --- aanet_proj: SEC=2 (weight-quantized) on all four layers ---
    gemm_mma<true,  true,  false, 2><<<dim3(16, rt), blk, SMEM>>>(AC1, W1c, b1, nullptr, AC2, nullptr, M, 1024, 512);
    gemm_mma<true,  true,  false, 2><<<dim3(16, rt), blk, SMEM>>>(AC2, W2c, b2, nullptr, AC1, nullptr, M, 1024, 1024);
    gemm_mma<true,  true,  false, 2><<<dim3(8,  rt), blk, SMEM>>>(AC1, W3c, b3, nullptr, AC2, nullptr, M, 512, 1024);
    gemm_mma<false, false, false, 2><<<dim3(2,  rt), blk, SMEM>>>(AC2, W4c, b4, feat, nullptr, nullptr, M, 80, 512);

    // --- GIN aggregation in 80-dim feat space: t = feat + segsum(feat[src]) ---
    k_init_t<<<cdiv(NN * 20, 256), blk>>>(feat, T, DEG, NN * 20, NN);
    k_scatter<<<cdiv((long long)EE * 20, 256), blk>>>(feat, EI, T, DEG, EE);

    // --- g = t @ Win + (1 + deg) * bin  (deg fixup fused; SEC=3, tiny) ---
    conv_act<<<cdiv((long long)M * 32, 256), blk>>>(T, AC1, M, 80, 128);
    gemm_mma<false, true,  true,  3><<<dim3(8, rt), blk, SMEM>>>(AC1, Winc, bin_, nullptr, AC2, DEG, M, 512, 128);

    // --- GIN MLP: SEC=2 ---
    gemm_mma<true,  true,  false, 2><<<dim3(8, rt), blk, SMEM>>>(AC2, Wg1c, bg1, nullptr, AC1, nullptr, M, 512, 512);
    gemm_mma<false, true,  false, 2><<<dim3(8, rt), blk, SMEM>>>(AC1, Wg2c, bg2, nullptr, AC2, nullptr, M, 512, 512);

    // --- out_net: SEC=3 (tiny) ---
    gemm_mma<false, false, false, 3><<<dim3(2, rt), blk, SMEM>>>(AC2, Woutc, bout, mask, nullptr, nullptr, M, 80, 512);
}

// round 13
// speedup vs baseline: 1.3816x; 1.3816x over previous
#include <cuda_runtime.h>
#include <cuda_fp16.h>
#include <cstdint>
#include <cstddef>

#define NN 50000
#define EE 800000

// ---------------- scratch (device globals: allocation-free) ----------------
__device__ __align__(256) __half g_ac1[(size_t)NN * 2048]; // [hi|lo] ping
__device__ __align__(256) __half g_ac2[(size_t)NN * 2048]; // [hi|lo] pong
__device__ __align__(256) float g_t  [(size_t)NN * 80];    // feat + agg
__device__ __align__(256) float g_deg[NN];
__device__ __align__(256) __half g_wc[8454144];            // weight convs

// ---------------- warp-MMA helpers (baseline sm_80+ PTX only) --------------
__device__ __forceinline__ void ldsm4(uint32_t* r, uint32_t addr) {
    asm volatile("ldmatrix.sync.aligned.m8n8.x4.shared.b16 {%0,%1,%2,%3}, [%4];"
                 : "=r"(r[0]), "=r"(r[1]), "=r"(r[2]), "=r"(r[3]) : "r"(addr));
}
__device__ __forceinline__ void mma_fp16(float* c, const uint32_t* a,
                                         uint32_t b0, uint32_t b1) {
    asm volatile(
        "mma.sync.aligned.m16n8k16.row.col.f32.f16.f16.f32 "
        "{%0,%1,%2,%3}, {%4,%5,%6,%7}, {%8,%9}, {%0,%1,%2,%3};"
        : "+f"(c[0]), "+f"(c[1]), "+f"(c[2]), "+f"(c[3])
        : "r"(a[0]), "r"(a[1]), "r"(a[2]), "r"(a[3]), "r"(b0), "r"(b1));
}

// ---------------- fp16 tensor-core GEMM -------------------------------------
// A: [M, 2*Kp] fp16 [Ahi|Alo].  Bw: [Np, 3*Kp] fp16 [Whi|Whi|Wlo] (transposed).
// SEC=1: K' = Kp   -> Ahi.Whi                (plain fp16,      ~3e-4/layer)
// SEC=2: K' = 2*Kp -> + Alo.Whi              (weight-quantized, ~1.6e-4)
// SEC=3: K' = 3*Kp -> + Ahi.Wlo              (near-fp32,       ~1e-6)
// CTA tile 128x128, warp tile 64x32, BK=64, 3-stage cp.async, 2 CTA/SM.
// SMEM rows: 128B data @ 144B pitch (odd 16B granules -> conflict-free ldsm).
// Inner loop: plain R8/R10 structure (ptxas schedules best; see R9/R11 PMs).
// Epilogue: X3 ? write [hi|lo] fp16 : write fp32. DEGFIX: +deg[r]*bias[c].
template <bool RELU, bool X3, bool DEGFIX, int SEC>
__global__ void __launch_bounds__(256, 2)
gemm_mma(const __half* __restrict__ A, const __half* __restrict__ Bw,
         const float* __restrict__ bias, float* __restrict__ Cf,
         __half* __restrict__ Cx, const float* __restrict__ deg,
         int M, int Nreal, int Kp)
{
    constexpr int STAGES = 3;
    constexpr int PITCH  = 144;
    constexpr int TILEB  = 128 * PITCH;   // 18432
    constexpr int STAGEB = 2 * TILEB;

    extern __shared__ char smem[];
    const uint32_t sbase = (uint32_t)__cvta_generic_to_shared(smem);

    const int tid  = threadIdx.x;
    const int lane = tid & 31;
    const int wid  = tid >> 5;
    const int wm   = wid >> 2;            // 0..1
    const int wn   = wid & 3;             // 0..3
    const int block_row = blockIdx.y * 128;
    const int block_col = blockIdx.x * 128;

    const int KCH = Kp >> 6;              // hi-section chunks
    const int KT  = SEC * KCH;            // total weight chunks
    const int ldA = 2 * Kp * 2;           // A row stride bytes (2 sections)
    const int ldB = 3 * Kp * 2;           // W row stride bytes (3 sections)
    const char* Ag = (const char*)A + (size_t)block_row * ldA;
    const char* Bg = (const char*)Bw + (size_t)block_col * ldB;

    // load mapping: row = tid/2, four 16B chunks at (tid&1)*64
    const int l_row = tid >> 1;
    const int l_c0  = (tid & 1) * 4;
    const int okA   = (block_row + l_row) < M ? 16 : 0;
    const char* ArowC = Ag + (size_t)((block_row + l_row) < M ? l_row : 0) * ldA;
    const char* BrowC = Bg + (size_t)l_row * ldB;

    auto load_stage = [&](int s, int kc) {
        int ka = (SEC == 3 && kc >= 2 * KCH) ? kc - 2 * KCH : kc;  // A map
        uint32_t abuf = sbase + s * STAGEB + l_row * PITCH;
        uint32_t bbuf = abuf + TILEB;
        const char* Ak = ArowC + ka * 128;
        const char* Bk = BrowC + kc * 128;
#pragma unroll
        for (int it = 0; it < 4; it++) {
            int c = l_c0 + it;
            asm volatile("cp.async.cg.shared.global [%0], [%1], 16, %2;"
                         :: "r"(abuf + c * 16), "l"(Ak + c * 16), "r"(okA));
            asm volatile("cp.async.cg.shared.global [%0], [%1], 16;"
                         :: "r"(bbuf + c * 16), "l"(Bk + c * 16));
        }
    };

    float acc[4][4][4];
#pragma unroll
    for (int i = 0; i < 4; i++)
#pragma unroll
        for (int j = 0; j < 4; j++)
#pragma unroll
            for (int k = 0; k < 4; k++) acc[i][j][k] = 0.f;

    load_stage(0, 0);
    asm volatile("cp.async.commit_group;" ::: "memory");
    if (KT > 1) load_stage(1, 1);
    asm volatile("cp.async.commit_group;" ::: "memory");

    const uint32_t lrow = lane & 15;
    const uint32_t lhi  = (lane >> 4) << 4;
    uint32_t aoff[4], boff[2];
#pragma unroll
    for (int mt = 0; mt < 4; mt++)
        aoff[mt] = (wm * 64 + mt * 16 + lrow) * PITCH + lhi;
#pragma unroll
    for (int nt = 0; nt < 2; nt++)
        boff[nt] = TILEB + (wn * 32 + nt * 16 + lrow) * PITCH + lhi;

    int slot = 0;
    for (int ks = 0; ks < KT; ks++) {
        asm volatile("cp.async.wait_group 1;" ::: "memory");
        __syncthreads();
        int kn = ks + STAGES - 1;
        int nslot = slot + 1 == STAGES ? 0 : slot + 1;
        int lslot = nslot + 1 == STAGES ? 0 : nslot + 1;
        if (kn < KT) load_stage(lslot, kn);
        asm volatile("cp.async.commit_group;" ::: "memory");

        uint32_t buf = sbase + slot * STAGEB;
#pragma unroll
        for (int kk = 0; kk < 4; kk++) {          // four k16 steps per chunk
            uint32_t col = kk * 32;
            uint32_t afr[4][4];
#pragma unroll
            for (int mt = 0; mt < 4; mt++)
                ldsm4(afr[mt], buf + aoff[mt] + col);
            uint32_t bq[2][4];
#pragma unroll
            for (int nt = 0; nt < 2; nt++)
                ldsm4(bq[nt], buf + boff[nt] + col);
#pragma unroll
            for (int mt = 0; mt < 4; mt++)
#pragma unroll
                for (int n8 = 0; n8 < 4; n8++)
                    mma_fp16(acc[mt][n8], afr[mt],
                             bq[n8 >> 1][n8 & 1], bq[n8 >> 1][(n8 & 1) + 2]);
        }
        slot = nslot;
    }

    // epilogue
    const int g = lane >> 2, t = lane & 3;
    const size_t ldx = (size_t)2 * Nreal;     // [hi|lo] output layout
#pragma unroll
    for (int mt = 0; mt < 4; mt++) {
#pragma unroll
        for (int n8 = 0; n8 < 4; n8++) {
            int c = block_col + wn * 32 + n8 * 8 + t * 2;
            if (c >= Nreal) continue;
            float bx = __ldg(bias + c), by = __ldg(bias + c + 1);
#pragma unroll
            for (int h = 0; h < 2; h++) {
                int r = block_row + wm * 64 + mt * 16 + g + h * 8;
                if (r >= M) continue;
                float vx = acc[mt][n8][h * 2 + 0] + bx;
                float vy = acc[mt][n8][h * 2 + 1] + by;
                if (DEGFIX) {
                    float dg = __ldg(deg + r);
                    vx += dg * bx;
                    vy += dg * by;
                }
                if (RELU) { vx = fmaxf(vx, 0.f); vy = fmaxf(vy, 0.f); }
                if (X3) {
                    __half hx = __float2half_rn(vx);
                    __half hy = __float2half_rn(vy);
                    __half lx = __float2half_rn(vx - __half2float(hx));
                    __half ly = __float2half_rn(vy - __half2float(hy));
                    __half2 hi; hi.x = hx; hi.y = hy;
                    __half2 lo; lo.x = lx; lo.y = ly;
                    __half* p = Cx + (size_t)r * ldx + c;
                    *reinterpret_cast<__half2*>(p) = hi;
                    *reinterpret_cast<__half2*>(p + Nreal) = lo;
                } else {
                    float2 v; v.x = vx; v.y = vy;
                    *reinterpret_cast<float2*>(Cf + (size_t)r * Nreal + c) = v;
                }
            }
        }
    }
}

// ---------------- fp32 -> split-fp16 [hi | lo] conversion (float4) ----------
__global__ void conv_act(const float* __restrict__ in, __half* __restrict__ out,
                         int M, int K, int Kp)
{
    int q = Kp >> 2;
    int idx = blockIdx.x * blockDim.x + threadIdx.x;
    if (idx >= M * q) return;
    int r = idx / q;
    int k4 = (idx - r * q) * 4;
    float4 x = make_float4(0.f, 0.f, 0.f, 0.f);
    if (k4 < K)
        x = *reinterpret_cast<const float4*>(in + (size_t)r * K + k4);
    __half2 h0, h1, l0, l1;
    h0.x = __float2half_rn(x.x); h0.y = __float2half_rn(x.y);
    h1.x = __float2half_rn(x.z); h1.y = __float2half_rn(x.w);
    l0.x = __float2half_rn(x.x - __half2float(h0.x));
    l0.y = __float2half_rn(x.y - __half2float(h0.y));
    l1.x = __float2half_rn(x.z - __half2float(h1.x));
    l1.y = __float2half_rn(x.w - __half2float(h1.y));
    __half* b = out + (size_t)r * 2 * Kp;
    reinterpret_cast<__half2*>(b + k4)[0] = h0;
    reinterpret_cast<__half2*>(b + k4)[1] = h1;
    reinterpret_cast<__half2*>(b + Kp + k4)[0] = l0;
    reinterpret_cast<__half2*>(b + Kp + k4)[1] = l1;
}

// ---------------- all weight conversions in ONE kernel ----------------------
// W[K,N] fp32 -> [Np, 3*Kp] fp16, row n = [hi | hi | lo] (pairs with act [hi|lo])
struct WDesc { const float* W; __half* out; int K, N, Kp, Np; };
struct WAll  { WDesc d[8]; };

__global__ void conv_wt_all(WAll wa)
{
    WDesc d = wa.d[blockIdx.y];
    int tot = d.Np * d.Kp;
    for (int idx = blockIdx.x * blockDim.x + threadIdx.x; idx < tot;
         idx += gridDim.x * blockDim.x) {
        int n = idx / d.Kp;
        int k = idx - n * d.Kp;
        float x = (k < d.K && n < d.N) ? d.W[(size_t)k * d.N + n] : 0.f;
        __half hi = __float2half_rn(x);
        __half lo = __float2half_rn(x - __half2float(hi));
        size_t b = (size_t)n * 3 * d.Kp;
        d.out[b + k] = hi;
        d.out[b + d.Kp + k] = hi;
        d.out[b + 2 * d.Kp + k] = lo;
    }
}

// ---------------- GIN aggregation on 80-dim feat ----------------------------
__global__ void k_init_t(const float* __restrict__ feat, float* __restrict__ t,
                         float* __restrict__ deg, int n4, int N)
{
    int i = blockIdx.x * blockDim.x + threadIdx.x;
    if (i < n4)
        reinterpret_cast<float4*>(t)[i] = reinterpret_cast<const float4*>(feat)[i];
    if (i < N) deg[i] = 0.f;
}

__global__ void k_scatter(const float* __restrict__ feat, const int* __restrict__ ei,
                          float* __restrict__ t, float* __restrict__ deg, int E)
{
    int i = blockIdx.x * blockDim.x + threadIdx.x;
    if (i >= E * 20) return;
    int e = i / 20;
    int c = i - e * 20;
    int s = ei[e];
    int d = ei[E + e];
    float4 v = *reinterpret_cast<const float4*>(feat + (size_t)s * 80 + c * 4);
    float* p = t + (size_t)d * 80 + c * 4;
    asm volatile("red.global.add.v4.f32 [%0], {%1, %2, %3, %4};"
                 :: "l"(p), "f"(v.x), "f"(v.y), "f"(v.z), "f"(v.w) : "memory");
    if (c == 0) atomicAdd(deg + d, 1.f);
}

// ---------------- launch ----------------------------------------------------
static inline unsigned cdiv(long long a, long long b) { return (unsigned)((a + b - 1) / b); }

extern "C" void kernel_launch(void* const* d_in, const int* in_sizes, int n_in,
                              void* d_out, int out_size)
{
    const float* P    = (const float*)d_in[0];
    const int*   EI   = (const int*)  d_in[1];
    const float* W1   = (const float*)d_in[2];
    const float* b1   = (const float*)d_in[3];
    const float* W2   = (const float*)d_in[4];
    const float* b2   = (const float*)d_in[5];
    const float* W3   = (const float*)d_in[6];
    const float* b3   = (const float*)d_in[7];
    const float* W4   = (const float*)d_in[8];
    const float* b4   = (const float*)d_in[9];
    const float* Win  = (const float*)d_in[10];
    const float* bin_ = (const float*)d_in[11];
    const float* Wg1  = (const float*)d_in[12];
    const float* bg1  = (const float*)d_in[13];
    const float* Wg2  = (const float*)d_in[14];
    const float* bg2  = (const float*)d_in[15];
    const float* Wout = (const float*)d_in[16];
    const float* bout = (const float*)d_in[17];

    float* out  = (float*)d_out;
    float* mask = out;
    float* feat = out + (size_t)NN * 80;

    float *T, *DEG;
    __half *AC1, *AC2, *WC;
    cudaGetSymbolAddress((void**)&T,   g_t);
    cudaGetSymbolAddress((void**)&DEG, g_deg);
    cudaGetSymbolAddress((void**)&AC1, g_ac1);
    cudaGetSymbolAddress((void**)&AC2, g_ac2);
    cudaGetSymbolAddress((void**)&WC,  g_wc);

    // weight conv buffer offsets (elements)
    __half* W1c   = WC + 0;        // 1024 x 1536
    __half* W2c   = WC + 1572864;  // 1024 x 3072
    __half* W3c   = WC + 4718592;  // 512 x 3072
    __half* W4c   = WC + 6291456;  // 128 x 1536
    __half* Winc  = WC + 6488064;  // 512 x 384
    __half* Wg1c  = WC + 6684672;  // 512 x 1536
    __half* Wg2c  = WC + 7471104;  // 512 x 1536
    __half* Woutc = WC + 8257536;  // 128 x 1536

    const int M = NN;
    const int SMEM = 3 * 2 * 128 * 144;   // 110592 B -> 2 CTA/SM
    cudaFuncSetAttribute(gemm_mma<true,  true,  false, 1>, cudaFuncAttributeMaxDynamicSharedMemorySize, SMEM);
    cudaFuncSetAttribute(gemm_mma<true,  true,  false, 2>, cudaFuncAttributeMaxDynamicSharedMemorySize, SMEM);
    cudaFuncSetAttribute(gemm_mma<false, false, false, 2>, cudaFuncAttributeMaxDynamicSharedMemorySize, SMEM);
    cudaFuncSetAttribute(gemm_mma<false, true,  false, 2>, cudaFuncAttributeMaxDynamicSharedMemorySize, SMEM);
    cudaFuncSetAttribute(gemm_mma<false, true,  true,  3>, cudaFuncAttributeMaxDynamicSharedMemorySize, SMEM);
    cudaFuncSetAttribute(gemm_mma<false, false, false, 3>, cudaFuncAttributeMaxDynamicSharedMemorySize, SMEM);

    const dim3 blk(256);
    const unsigned rt = cdiv(M, 128);

    // --- all weight conversions (one kernel) ---
    WAll wa;
    wa.d[0] = { W1,   W1c,    512, 1024,  512, 1024 };
    wa.d[1] = { W2,   W2c,   1024, 1024, 1024, 1024 };
    wa.d[2] = { W3,   W3c,   1024,  512, 1024,  512 };
    wa.d[3] = { W4,   W4c,    512,   80,  512,  128 };
    wa.d[4] = { Win,  Winc,    80,  512,  128,  512 };
    wa.d[5] = { Wg1,  Wg1c,   512,  512,  512,  512 };
    wa.d[6] = { Wg2,  Wg2c,   512,  512,  512,  512 };
    wa.d[7] = { Wout, Woutc,  512,   80,  512,  128 };
    conv_wt_all<<<dim3(2048, 8), blk>>>(wa);

    // --- expand P to [hi|lo] ---
    conv_act<<<cdiv((long long)M * 128, 256), blk>>>(P, AC1, M, 512, 512);

    // --- aanet_proj: SEC=1 on the two biggest layers, SEC=2 on the rest ---
    gemm_mma<true,  true,  false, 1><<<dim3(8, rt), blk, SMEM>>>(AC1, W1c, b1, nullptr, AC2, nullptr, M, 1024, 512);
    gemm_mma<true,  true,  false, 1><<<dim3(8, rt), blk, SMEM>>>(AC2, W2c, b2, nullptr, AC1, nullptr, M, 1024, 1024);
    gemm_mma<true,  true,  false, 2><<<dim3(4, rt), blk, SMEM>>>(AC1, W3c, b3, nullptr, AC2, nullptr, M, 512, 1024);
    gemm_mma<false, false, false, 2><<<dim3(1, rt), blk, SMEM>>>(AC2, W4c, b4, feat, nullptr, nullptr, M, 80, 512);

    // --- GIN aggregation in 80-dim feat space: t = feat + segsum(feat[src]) ---
    k_init_t<<<cdiv(NN * 20, 256), blk>>>(feat, T, DEG, NN * 20, NN);
    k_scatter<<<cdiv((long long)EE * 20, 256), blk>>>(feat, EI, T, DEG, EE);

    // --- g = t @ Win + (1 + deg) * bin  (deg fixup fused; SEC=3, tiny) ---
    conv_act<<<cdiv((long long)M * 32, 256), blk>>>(T, AC1, M, 80, 128);
    gemm_mma<false, true,  true,  3><<<dim3(4, rt), blk, SMEM>>>(AC1, Winc, bin_, nullptr, AC2, DEG, M, 512, 128);

    // --- GIN MLP: SEC=2 ---
    gemm_mma<true,  true,  false, 2><<<dim3(4, rt), blk, SMEM>>>(AC2, Wg1c, bg1, nullptr, AC1, nullptr, M, 512, 512);
    gemm_mma<false, true,  false, 2><<<dim3(4, rt), blk, SMEM>>>(AC1, Wg2c, bg2, nullptr, AC2, nullptr, M, 512, 512);

    // --- out_net: SEC=3 (tiny) ---
    gemm_mma<false, false, false, 3><<<dim3(1, rt), blk, SMEM>>>(AC2, Woutc, bout, mask, nullptr, nullptr, M, 80, 512);
}

// round 14
// speedup vs baseline: 1.7453x; 1.2633x over previous
#include <cuda_runtime.h>
#include <cuda_fp16.h>
#include <cstdint>
#include <cstddef>

#define NN 50000
#define EE 800000

// ---------------- scratch (device globals: allocation-free) ----------------
__device__ __align__(256) __half g_ac1[(size_t)NN * 2048]; // [hi|lo] ping
__device__ __align__(256) __half g_ac2[(size_t)NN * 2048]; // [hi|lo] pong
__device__ __align__(256) float g_t  [(size_t)NN * 80];    // feat + agg
__device__ __align__(256) float g_deg[NN];
__device__ __align__(256) __half g_wc[8454144];            // weight convs

// ---------------- warp-MMA helpers (baseline sm_80+ PTX only) --------------
__device__ __forceinline__ void ldsm4(uint32_t* r, uint32_t addr) {
    asm volatile("ldmatrix.sync.aligned.m8n8.x4.shared.b16 {%0,%1,%2,%3}, [%4];"
                 : "=r"(r[0]), "=r"(r[1]), "=r"(r[2]), "=r"(r[3]) : "r"(addr));
}
__device__ __forceinline__ void mma_fp16(float* c, const uint32_t* a,
                                         uint32_t b0, uint32_t b1) {
    asm volatile(
        "mma.sync.aligned.m16n8k16.row.col.f32.f16.f16.f32 "
        "{%0,%1,%2,%3}, {%4,%5,%6,%7}, {%8,%9}, {%0,%1,%2,%3};"
        : "+f"(c[0]), "+f"(c[1]), "+f"(c[2]), "+f"(c[3])
        : "r"(a[0]), "r"(a[1]), "r"(a[2]), "r"(a[3]), "r"(b0), "r"(b1));
}

// ---------------- fp16 tensor-core GEMM -------------------------------------
// A: [M, 2*Kp] fp16 [Ahi|Alo].  Bw: [Np, 3*Kp] fp16 [Whi|Whi|Wlo] (transposed).
// SEC=1: K' = Kp   -> Ahi.Whi                (plain fp16,      ~2-3e-4/layer)
// SEC=2: K' = 2*Kp -> + Alo.Whi              (weight-quantized, ~1.6e-4)
// SEC=3: K' = 3*Kp -> + Ahi.Wlo              (near-fp32,       ~1e-6)
// CTA tile 128x128, warp tile 64x32, BK=64, 3-stage cp.async, 2 CTA/SM.
// SMEM rows: 128B data @ 144B pitch (odd 16B granules -> conflict-free ldsm).
// Inner loop: plain R8/R10 structure (ptxas schedules best; see R9/R11 PMs).
// Epilogue: X3 ? write [hi|lo] fp16 : write fp32. DEGFIX: +deg[r]*bias[c].
template <bool RELU, bool X3, bool DEGFIX, int SEC>
__global__ void __launch_bounds__(256, 2)
gemm_mma(const __half* __restrict__ A, const __half* __restrict__ Bw,
         const float* __restrict__ bias, float* __restrict__ Cf,
         __half* __restrict__ Cx, const float* __restrict__ deg,
         int M, int Nreal, int Kp)
{
    constexpr int STAGES = 3;
    constexpr int PITCH  = 144;
    constexpr int TILEB  = 128 * PITCH;   // 18432
    constexpr int STAGEB = 2 * TILEB;

    extern __shared__ char smem[];
    const uint32_t sbase = (uint32_t)__cvta_generic_to_shared(smem);

    const int tid  = threadIdx.x;
    const int lane = tid & 31;
    const int wid  = tid >> 5;
    const int wm   = wid >> 2;            // 0..1
    const int wn   = wid & 3;             // 0..3
    const int block_row = blockIdx.y * 128;
    const int block_col = blockIdx.x * 128;

    const int KCH = Kp >> 6;              // hi-section chunks
    const int KT  = SEC * KCH;            // total weight chunks
    const int ldA = 2 * Kp * 2;           // A row stride bytes (2 sections)
    const int ldB = 3 * Kp * 2;           // W row stride bytes (3 sections)
    const char* Ag = (const char*)A + (size_t)block_row * ldA;
    const char* Bg = (const char*)Bw + (size_t)block_col * ldB;

    // load mapping: row = tid/2, four 16B chunks at (tid&1)*64
    const int l_row = tid >> 1;
    const int l_c0  = (tid & 1) * 4;
    const int okA   = (block_row + l_row) < M ? 16 : 0;
    const char* ArowC = Ag + (size_t)((block_row + l_row) < M ? l_row : 0) * ldA;
    const char* BrowC = Bg + (size_t)l_row * ldB;

    auto load_stage = [&](int s, int kc) {
        int ka = (SEC == 3 && kc >= 2 * KCH) ? kc - 2 * KCH : kc;  // A map
        uint32_t abuf = sbase + s * STAGEB + l_row * PITCH;
        uint32_t bbuf = abuf + TILEB;
        const char* Ak = ArowC + ka * 128;
        const char* Bk = BrowC + kc * 128;
#pragma unroll
        for (int it = 0; it < 4; it++) {
            int c = l_c0 + it;
            asm volatile("cp.async.cg.shared.global [%0], [%1], 16, %2;"
                         :: "r"(abuf + c * 16), "l"(Ak + c * 16), "r"(okA));
            asm volatile("cp.async.cg.shared.global [%0], [%1], 16;"
                         :: "r"(bbuf + c * 16), "l"(Bk + c * 16));
        }
    };

    float acc[4][4][4];
#pragma unroll
    for (int i = 0; i < 4; i++)
#pragma unroll
        for (int j = 0; j < 4; j++)
#pragma unroll
            for (int k = 0; k < 4; k++) acc[i][j][k] = 0.f;

    load_stage(0, 0);
    asm volatile("cp.async.commit_group;" ::: "memory");
    if (KT > 1) load_stage(1, 1);
    asm volatile("cp.async.commit_group;" ::: "memory");

    const uint32_t lrow = lane & 15;
    const uint32_t lhi  = (lane >> 4) << 4;
    uint32_t aoff[4], boff[2];
#pragma unroll
    for (int mt = 0; mt < 4; mt++)
        aoff[mt] = (wm * 64 + mt * 16 + lrow) * PITCH + lhi;
#pragma unroll
    for (int nt = 0; nt < 2; nt++)
        boff[nt] = TILEB + (wn * 32 + nt * 16 + lrow) * PITCH + lhi;

    int slot = 0;
    for (int ks = 0; ks < KT; ks++) {
        asm volatile("cp.async.wait_group 1;" ::: "memory");
        __syncthreads();
        int kn = ks + STAGES - 1;
        int nslot = slot + 1 == STAGES ? 0 : slot + 1;
        int lslot = nslot + 1 == STAGES ? 0 : nslot + 1;
        if (kn < KT) load_stage(lslot, kn);
        asm volatile("cp.async.commit_group;" ::: "memory");

        uint32_t buf = sbase + slot * STAGEB;
#pragma unroll
        for (int kk = 0; kk < 4; kk++) {          // four k16 steps per chunk
            uint32_t col = kk * 32;
            uint32_t afr[4][4];
#pragma unroll
            for (int mt = 0; mt < 4; mt++)
                ldsm4(afr[mt], buf + aoff[mt] + col);
            uint32_t bq[2][4];
#pragma unroll
            for (int nt = 0; nt < 2; nt++)
                ldsm4(bq[nt], buf + boff[nt] + col);
#pragma unroll
            for (int mt = 0; mt < 4; mt++)
#pragma unroll
                for (int n8 = 0; n8 < 4; n8++)
                    mma_fp16(acc[mt][n8], afr[mt],
                             bq[n8 >> 1][n8 & 1], bq[n8 >> 1][(n8 & 1) + 2]);
        }
        slot = nslot;
    }

    // epilogue
    const int g = lane >> 2, t = lane & 3;
    const size_t ldx = (size_t)2 * Nreal;     // [hi|lo] output layout
#pragma unroll
    for (int mt = 0; mt < 4; mt++) {
#pragma unroll
        for (int n8 = 0; n8 < 4; n8++) {
            int c = block_col + wn * 32 + n8 * 8 + t * 2;
            if (c >= Nreal) continue;
            float bx = __ldg(bias + c), by = __ldg(bias + c + 1);
#pragma unroll
            for (int h = 0; h < 2; h++) {
                int r = block_row + wm * 64 + mt * 16 + g + h * 8;
                if (r >= M) continue;
                float vx = acc[mt][n8][h * 2 + 0] + bx;
                float vy = acc[mt][n8][h * 2 + 1] + by;
                if (DEGFIX) {
                    float dg = __ldg(deg + r);
                    vx += dg * bx;
                    vy += dg * by;
                }
                if (RELU) { vx = fmaxf(vx, 0.f); vy = fmaxf(vy, 0.f); }
                if (X3) {
                    __half hx = __float2half_rn(vx);
                    __half hy = __float2half_rn(vy);
                    __half lx = __float2half_rn(vx - __half2float(hx));
                    __half ly = __float2half_rn(vy - __half2float(hy));
                    __half2 hi; hi.x = hx; hi.y = hy;
                    __half2 lo; lo.x = lx; lo.y = ly;
                    __half* p = Cx + (size_t)r * ldx + c;
                    *reinterpret_cast<__half2*>(p) = hi;
                    *reinterpret_cast<__half2*>(p + Nreal) = lo;
                } else {
                    float2 v; v.x = vx; v.y = vy;
                    *reinterpret_cast<float2*>(Cf + (size_t)r * Nreal + c) = v;
                }
            }
        }
    }
}

// ---------------- fp32 -> split-fp16 [hi | lo] conversion (float4) ----------
__global__ void conv_act(const float* __restrict__ in, __half* __restrict__ out,
                         int M, int K, int Kp)
{
    int q = Kp >> 2;
    int idx = blockIdx.x * blockDim.x + threadIdx.x;
    if (idx >= M * q) return;
    int r = idx / q;
    int k4 = (idx - r * q) * 4;
    float4 x = make_float4(0.f, 0.f, 0.f, 0.f);
    if (k4 < K)
        x = *reinterpret_cast<const float4*>(in + (size_t)r * K + k4);
    __half2 h0, h1, l0, l1;
    h0.x = __float2half_rn(x.x); h0.y = __float2half_rn(x.y);
    h1.x = __float2half_rn(x.z); h1.y = __float2half_rn(x.w);
    l0.x = __float2half_rn(x.x - __half2float(h0.x));
    l0.y = __float2half_rn(x.y - __half2float(h0.y));
    l1.x = __float2half_rn(x.z - __half2float(h1.x));
    l1.y = __float2half_rn(x.w - __half2float(h1.y));
    __half* b = out + (size_t)r * 2 * Kp;
    reinterpret_cast<__half2*>(b + k4)[0] = h0;
    reinterpret_cast<__half2*>(b + k4)[1] = h1;
    reinterpret_cast<__half2*>(b + Kp + k4)[0] = l0;
    reinterpret_cast<__half2*>(b + Kp + k4)[1] = l1;
}

// ---------------- all weight conversions in ONE kernel ----------------------
// W[K,N] fp32 -> [Np, 3*Kp] fp16, row n = [hi | hi | lo] (pairs with act [hi|lo])
struct WDesc { const float* W; __half* out; int K, N, Kp, Np; };
struct WAll  { WDesc d[8]; };

__global__ void conv_wt_all(WAll wa)
{
    WDesc d = wa.d[blockIdx.y];
    int tot = d.Np * d.Kp;
    for (int idx = blockIdx.x * blockDim.x + threadIdx.x; idx < tot;
         idx += gridDim.x * blockDim.x) {
        int n = idx / d.Kp;
        int k = idx - n * d.Kp;
        float x = (k < d.K && n < d.N) ? d.W[(size_t)k * d.N + n] : 0.f;
        __half hi = __float2half_rn(x);
        __half lo = __float2half_rn(x - __half2float(hi));
        size_t b = (size_t)n * 3 * d.Kp;
        d.out[b + k] = hi;
        d.out[b + d.Kp + k] = hi;
        d.out[b + 2 * d.Kp + k] = lo;
    }
}

// ---------------- GIN aggregation on 80-dim feat ----------------------------
__global__ void k_init_t(const float* __restrict__ feat, float* __restrict__ t,
                         float* __restrict__ deg, int n4, int N)
{
    int i = blockIdx.x * blockDim.x + threadIdx.x;
    if (i < n4)
        reinterpret_cast<float4*>(t)[i] = reinterpret_cast<const float4*>(feat)[i];
    if (i < N) deg[i] = 0.f;
}

__global__ void k_scatter(const float* __restrict__ feat, const int* __restrict__ ei,
                          float* __restrict__ t, float* __restrict__ deg, int E)
{
    int i = blockIdx.x * blockDim.x + threadIdx.x;
    if (i >= E * 20) return;
    int e = i / 20;
    int c = i - e * 20;
    int s = ei[e];
    int d = ei[E + e];
    float4 v = *reinterpret_cast<const float4*>(feat + (size_t)s * 80 + c * 4);
    float* p = t + (size_t)d * 80 + c * 4;
    asm volatile("red.global.add.v4.f32 [%0], {%1, %2, %3, %4};"
                 :: "l"(p), "f"(v.x), "f"(v.y), "f"(v.z), "f"(v.w) : "memory");
    if (c == 0) atomicAdd(deg + d, 1.f);
}

// ---------------- launch ----------------------------------------------------
static inline unsigned cdiv(long long a, long long b) { return (unsigned)((a + b - 1) / b); }

extern "C" void kernel_launch(void* const* d_in, const int* in_sizes, int n_in,
                              void* d_out, int out_size)
{
    const float* P    = (const float*)d_in[0];
    const int*   EI   = (const int*)  d_in[1];
    const float* W1   = (const float*)d_in[2];
    const float* b1   = (const float*)d_in[3];
    const float* W2   = (const float*)d_in[4];
    const float* b2   = (const float*)d_in[5];
    const float* W3   = (const float*)d_in[6];
    const float* b3   = (const float*)d_in[7];
    const float* W4   = (const float*)d_in[8];
    const float* b4   = (const float*)d_in[9];
    const float* Win  = (const float*)d_in[10];
    const float* bin_ = (const float*)d_in[11];
    const float* Wg1  = (const float*)d_in[12];
    const float* bg1  = (const float*)d_in[13];
    const float* Wg2  = (const float*)d_in[14];
    const float* bg2  = (const float*)d_in[15];
    const float* Wout = (const float*)d_in[16];
    const float* bout = (const float*)d_in[17];

    float* out  = (float*)d_out;
    float* mask = out;
    float* feat = out + (size_t)NN * 80;

    float *T, *DEG;
    __half *AC1, *AC2, *WC;
    cudaGetSymbolAddress((void**)&T,   g_t);
    cudaGetSymbolAddress((void**)&DEG, g_deg);
    cudaGetSymbolAddress((void**)&AC1, g_ac1);
    cudaGetSymbolAddress((void**)&AC2, g_ac2);
    cudaGetSymbolAddress((void**)&WC,  g_wc);

    // weight conv buffer offsets (elements)
    __half* W1c   = WC + 0;        // 1024 x 1536
    __half* W2c   = WC + 1572864;  // 1024 x 3072
    __half* W3c   = WC + 4718592;  // 512 x 3072
    __half* W4c   = WC + 6291456;  // 128 x 1536
    __half* Winc  = WC + 6488064;  // 512 x 384
    __half* Wg1c  = WC + 6684672;  // 512 x 1536
    __half* Wg2c  = WC + 7471104;  // 512 x 1536
    __half* Woutc = WC + 8257536;  // 128 x 1536

    const int M = NN;
    const int SMEM = 3 * 2 * 128 * 144;   // 110592 B -> 2 CTA/SM
    cudaFuncSetAttribute(gemm_mma<true,  true,  false, 1>, cudaFuncAttributeMaxDynamicSharedMemorySize, SMEM);
    cudaFuncSetAttribute(gemm_mma<false, true,  false, 1>, cudaFuncAttributeMaxDynamicSharedMemorySize, SMEM);
    cudaFuncSetAttribute(gemm_mma<false, false, false, 2>, cudaFuncAttributeMaxDynamicSharedMemorySize, SMEM);
    cudaFuncSetAttribute(gemm_mma<false, true,  true,  3>, cudaFuncAttributeMaxDynamicSharedMemorySize, SMEM);
    cudaFuncSetAttribute(gemm_mma<false, false, false, 3>, cudaFuncAttributeMaxDynamicSharedMemorySize, SMEM);

    const dim3 blk(256);
    const unsigned rt = cdiv(M, 128);

    // --- all weight conversions (one kernel) ---
    WAll wa;
    wa.d[0] = { W1,   W1c,    512, 1024,  512, 1024 };
    wa.d[1] = { W2,   W2c,   1024, 1024, 1024, 1024 };
    wa.d[2] = { W3,   W3c,   1024,  512, 1024,  512 };
    wa.d[3] = { W4,   W4c,    512,   80,  512,  128 };
    wa.d[4] = { Win,  Winc,    80,  512,  128,  512 };
    wa.d[5] = { Wg1,  Wg1c,   512,  512,  512,  512 };
    wa.d[6] = { Wg2,  Wg2c,   512,  512,  512,  512 };
    wa.d[7] = { Wout, Woutc,  512,   80,  512,  128 };
    conv_wt_all<<<dim3(2048, 8), blk>>>(wa);

    // --- expand P to [hi|lo] ---
    conv_act<<<cdiv((long long)M * 128, 256), blk>>>(P, AC1, M, 512, 512);

    // --- aanet_proj: SEC=1 on G1/G2/G3, SEC=2 on G4 (writes feat output) ---
    gemm_mma<true,  true,  false, 1><<<dim3(8, rt), blk, SMEM>>>(AC1, W1c, b1, nullptr, AC2, nullptr, M, 1024, 512);
    gemm_mma<true,  true,  false, 1><<<dim3(8, rt), blk, SMEM>>>(AC2, W2c, b2, nullptr, AC1, nullptr, M, 1024, 1024);
    gemm_mma<true,  true,  false, 1><<<dim3(4, rt), blk, SMEM>>>(AC1, W3c, b3, nullptr, AC2, nullptr, M, 512, 1024);
    gemm_mma<false, false, false, 2><<<dim3(1, rt), blk, SMEM>>>(AC2, W4c, b4, feat, nullptr, nullptr, M, 80, 512);

    // --- GIN aggregation in 80-dim feat space: t = feat + segsum(feat[src]) ---
    k_init_t<<<cdiv(NN * 20, 256), blk>>>(feat, T, DEG, NN * 20, NN);
    k_scatter<<<cdiv((long long)EE * 20, 256), blk>>>(feat, EI, T, DEG, EE);

    // --- g = t @ Win + (1 + deg) * bin  (deg fixup fused; SEC=3, tiny) ---
    conv_act<<<cdiv((long long)M * 32, 256), blk>>>(T, AC1, M, 80, 128);
    gemm_mma<false, true,  true,  3><<<dim3(4, rt), blk, SMEM>>>(AC1, Winc, bin_, nullptr, AC2, DEG, M, 512, 128);

    // --- GIN MLP: SEC=1 ---
    gemm_mma<true,  true,  false, 1><<<dim3(4, rt), blk, SMEM>>>(AC2, Wg1c, bg1, nullptr, AC1, nullptr, M, 512, 512);
    gemm_mma<false, true,  false, 1><<<dim3(4, rt), blk, SMEM>>>(AC1, Wg2c, bg2, nullptr, AC2, nullptr, M, 512, 512);

    // --- out_net: SEC=3 (tiny) ---
    gemm_mma<false, false, false, 3><<<dim3(1, rt), blk, SMEM>>>(AC2, Woutc, bout, mask, nullptr, nullptr, M, 80, 512);
}

// round 15
// speedup vs baseline: 1.9093x; 1.0940x over previous
#include <cuda_runtime.h>
#include <cuda_fp16.h>
#include <cstdint>
#include <cstddef>

#define NN 50000
#define EE 800000

// ---------------- scratch (device globals: allocation-free) ----------------
__device__ __align__(256) __half g_ac1[(size_t)NN * 2048]; // [hi|lo] ping
__device__ __align__(256) __half g_ac2[(size_t)NN * 2048]; // [hi|lo] pong
__device__ __align__(256) float g_t  [(size_t)NN * 80];    // feat + agg
__device__ __align__(256) float g_deg[NN];
__device__ __align__(256) __half g_wc[8454144];            // weight convs

// ---------------- warp-MMA helpers (baseline sm_80+ PTX only) --------------
__device__ __forceinline__ void ldsm4(uint32_t* r, uint32_t addr) {
    asm volatile("ldmatrix.sync.aligned.m8n8.x4.shared.b16 {%0,%1,%2,%3}, [%4];"
                 : "=r"(r[0]), "=r"(r[1]), "=r"(r[2]), "=r"(r[3]) : "r"(addr));
}
__device__ __forceinline__ void mma_fp16(float* c, const uint32_t* a,
                                         uint32_t b0, uint32_t b1) {
    asm volatile(
        "mma.sync.aligned.m16n8k16.row.col.f32.f16.f16.f32 "
        "{%0,%1,%2,%3}, {%4,%5,%6,%7}, {%8,%9}, {%0,%1,%2,%3};"
        : "+f"(c[0]), "+f"(c[1]), "+f"(c[2]), "+f"(c[3])
        : "r"(a[0]), "r"(a[1]), "r"(a[2]), "r"(a[3]), "r"(b0), "r"(b1));
}

// ---------------- fp16 tensor-core GEMM -------------------------------------
// A: [M, 2*Kp] fp16 [Ahi|Alo].  Bw: [Np, 3*Kp] fp16 [Whi|Whi|Wlo] (transposed).
// SEC=1: K' = Kp   -> Ahi.Whi                (plain fp16,      ~1-3e-4/layer)
// SEC=2: K' = 2*Kp -> + Alo.Whi              (weight-quantized, ~1.6e-4)
// SEC=3: K' = 3*Kp -> + Ahi.Wlo              (near-fp32,       ~1e-6)
// CTA tile 128x128, warp tile 64x32, BK=64, 3-stage cp.async, 2 CTA/SM.
// SMEM rows: 128B data @ 144B pitch (odd 16B granules -> conflict-free ldsm).
// Inner loop: plain R8/R10 structure (ptxas schedules best; see R9/R11 PMs).
// Epilogue: X3 ? write [hi|lo] fp16 : write fp32. DEGFIX: +deg[r]*bias[c].
template <bool RELU, bool X3, bool DEGFIX, int SEC>
__global__ void __launch_bounds__(256, 2)
gemm_mma(const __half* __restrict__ A, const __half* __restrict__ Bw,
         const float* __restrict__ bias, float* __restrict__ Cf,
         __half* __restrict__ Cx, const float* __restrict__ deg,
         int M, int Nreal, int Kp)
{
    constexpr int STAGES = 3;
    constexpr int PITCH  = 144;
    constexpr int TILEB  = 128 * PITCH;   // 18432
    constexpr int STAGEB = 2 * TILEB;

    extern __shared__ char smem[];
    const uint32_t sbase = (uint32_t)__cvta_generic_to_shared(smem);

    const int tid  = threadIdx.x;
    const int lane = tid & 31;
    const int wid  = tid >> 5;
    const int wm   = wid >> 2;            // 0..1
    const int wn   = wid & 3;             // 0..3
    const int block_row = blockIdx.y * 128;
    const int block_col = blockIdx.x * 128;

    const int KCH = Kp >> 6;              // hi-section chunks
    const int KT  = SEC * KCH;            // total weight chunks
    const int ldA = 2 * Kp * 2;           // A row stride bytes (2 sections)
    const int ldB = 3 * Kp * 2;           // W row stride bytes (3 sections)
    const char* Ag = (const char*)A + (size_t)block_row * ldA;
    const char* Bg = (const char*)Bw + (size_t)block_col * ldB;

    // load mapping: row = tid/2, four 16B chunks at (tid&1)*64
    const int l_row = tid >> 1;
    const int l_c0  = (tid & 1) * 4;
    const int okA   = (block_row + l_row) < M ? 16 : 0;
    const char* ArowC = Ag + (size_t)((block_row + l_row) < M ? l_row : 0) * ldA;
    const char* BrowC = Bg + (size_t)l_row * ldB;

    auto load_stage = [&](int s, int kc) {
        int ka = (SEC == 3 && kc >= 2 * KCH) ? kc - 2 * KCH : kc;  // A map
        uint32_t abuf = sbase + s * STAGEB + l_row * PITCH;
        uint32_t bbuf = abuf + TILEB;
        const char* Ak = ArowC + ka * 128;
        const char* Bk = BrowC + kc * 128;
#pragma unroll
        for (int it = 0; it < 4; it++) {
            int c = l_c0 + it;
            asm volatile("cp.async.cg.shared.global [%0], [%1], 16, %2;"
                         :: "r"(abuf + c * 16), "l"(Ak + c * 16), "r"(okA));
            asm volatile("cp.async.cg.shared.global [%0], [%1], 16;"
                         :: "r"(bbuf + c * 16), "l"(Bk + c * 16));
        }
    };

    float acc[4][4][4];
#pragma unroll
    for (int i = 0; i < 4; i++)
#pragma unroll
        for (int j = 0; j < 4; j++)
#pragma unroll
            for (int k = 0; k < 4; k++) acc[i][j][k] = 0.f;

    load_stage(0, 0);
    asm volatile("cp.async.commit_group;" ::: "memory");
    if (KT > 1) load_stage(1, 1);
    asm volatile("cp.async.commit_group;" ::: "memory");

    const uint32_t lrow = lane & 15;
    const uint32_t lhi  = (lane >> 4) << 4;
    uint32_t aoff[4], boff[2];
#pragma unroll
    for (int mt = 0; mt < 4; mt++)
        aoff[mt] = (wm * 64 + mt * 16 + lrow) * PITCH + lhi;
#pragma unroll
    for (int nt = 0; nt < 2; nt++)
        boff[nt] = TILEB + (wn * 32 + nt * 16 + lrow) * PITCH + lhi;

    int slot = 0;
    for (int ks = 0; ks < KT; ks++) {
        asm volatile("cp.async.wait_group 1;" ::: "memory");
        __syncthreads();
        int kn = ks + STAGES - 1;
        int nslot = slot + 1 == STAGES ? 0 : slot + 1;
        int lslot = nslot + 1 == STAGES ? 0 : nslot + 1;
        if (kn < KT) load_stage(lslot, kn);
        asm volatile("cp.async.commit_group;" ::: "memory");

        uint32_t buf = sbase + slot * STAGEB;
#pragma unroll
        for (int kk = 0; kk < 4; kk++) {          // four k16 steps per chunk
            uint32_t col = kk * 32;
            uint32_t afr[4][4];
#pragma unroll
            for (int mt = 0; mt < 4; mt++)
                ldsm4(afr[mt], buf + aoff[mt] + col);
            uint32_t bq[2][4];
#pragma unroll
            for (int nt = 0; nt < 2; nt++)
                ldsm4(bq[nt], buf + boff[nt] + col);
#pragma unroll
            for (int mt = 0; mt < 4; mt++)
#pragma unroll
                for (int n8 = 0; n8 < 4; n8++)
                    mma_fp16(acc[mt][n8], afr[mt],
                             bq[n8 >> 1][n8 & 1], bq[n8 >> 1][(n8 & 1) + 2]);
        }
        slot = nslot;
    }

    // epilogue
    const int g = lane >> 2, t = lane & 3;
    const size_t ldx = (size_t)2 * Nreal;     // [hi|lo] output layout
#pragma unroll
    for (int mt = 0; mt < 4; mt++) {
#pragma unroll
        for (int n8 = 0; n8 < 4; n8++) {
            int c = block_col + wn * 32 + n8 * 8 + t * 2;
            if (c >= Nreal) continue;
            float bx = __ldg(bias + c), by = __ldg(bias + c + 1);
#pragma unroll
            for (int h = 0; h < 2; h++) {
                int r = block_row + wm * 64 + mt * 16 + g + h * 8;
                if (r >= M) continue;
                float vx = acc[mt][n8][h * 2 + 0] + bx;
                float vy = acc[mt][n8][h * 2 + 1] + by;
                if (DEGFIX) {
                    float dg = __ldg(deg + r);
                    vx += dg * bx;
                    vy += dg * by;
                }
                if (RELU) { vx = fmaxf(vx, 0.f); vy = fmaxf(vy, 0.f); }
                if (X3) {
                    __half hx = __float2half_rn(vx);
                    __half hy = __float2half_rn(vy);
                    __half lx = __float2half_rn(vx - __half2float(hx));
                    __half ly = __float2half_rn(vy - __half2float(hy));
                    __half2 hi; hi.x = hx; hi.y = hy;
                    __half2 lo; lo.x = lx; lo.y = ly;
                    __half* p = Cx + (size_t)r * ldx + c;
                    *reinterpret_cast<__half2*>(p) = hi;
                    *reinterpret_cast<__half2*>(p + Nreal) = lo;
                } else {
                    float2 v; v.x = vx; v.y = vy;
                    *reinterpret_cast<float2*>(Cf + (size_t)r * Nreal + c) = v;
                }
            }
        }
    }
}

// ---------------- fp32 -> split-fp16 [hi | lo] conversion (float4) ----------
__global__ void conv_act(const float* __restrict__ in, __half* __restrict__ out,
                         int M, int K, int Kp)
{
    int q = Kp >> 2;
    int idx = blockIdx.x * blockDim.x + threadIdx.x;
    if (idx >= M * q) return;
    int r = idx / q;
    int k4 = (idx - r * q) * 4;
    float4 x = make_float4(0.f, 0.f, 0.f, 0.f);
    if (k4 < K)
        x = *reinterpret_cast<const float4*>(in + (size_t)r * K + k4);
    __half2 h0, h1, l0, l1;
    h0.x = __float2half_rn(x.x); h0.y = __float2half_rn(x.y);
    h1.x = __float2half_rn(x.z); h1.y = __float2half_rn(x.w);
    l0.x = __float2half_rn(x.x - __half2float(h0.x));
    l0.y = __float2half_rn(x.y - __half2float(h0.y));
    l1.x = __float2half_rn(x.z - __half2float(h1.x));
    l1.y = __float2half_rn(x.w - __half2float(h1.y));
    __half* b = out + (size_t)r * 2 * Kp;
    reinterpret_cast<__half2*>(b + k4)[0] = h0;
    reinterpret_cast<__half2*>(b + k4)[1] = h1;
    reinterpret_cast<__half2*>(b + Kp + k4)[0] = l0;
    reinterpret_cast<__half2*>(b + Kp + k4)[1] = l1;
}

// ---------------- all weight conversions in ONE kernel ----------------------
// W[K,N] fp32 -> [Np, 3*Kp] fp16, row n = [hi | hi | lo] (pairs with act [hi|lo])
struct WDesc { const float* W; __half* out; int K, N, Kp, Np; };
struct WAll  { WDesc d[8]; };

__global__ void conv_wt_all(WAll wa)
{
    WDesc d = wa.d[blockIdx.y];
    int tot = d.Np * d.Kp;
    for (int idx = blockIdx.x * blockDim.x + threadIdx.x; idx < tot;
         idx += gridDim.x * blockDim.x) {
        int n = idx / d.Kp;
        int k = idx - n * d.Kp;
        float x = (k < d.K && n < d.N) ? d.W[(size_t)k * d.N + n] : 0.f;
        __half hi = __float2half_rn(x);
        __half lo = __float2half_rn(x - __half2float(hi));
        size_t b = (size_t)n * 3 * d.Kp;
        d.out[b + k] = hi;
        d.out[b + d.Kp + k] = hi;
        d.out[b + 2 * d.Kp + k] = lo;
    }
}

// ---------------- GIN aggregation on 80-dim feat ----------------------------
__global__ void k_init_t(const float* __restrict__ feat, float* __restrict__ t,
                         float* __restrict__ deg, int n4, int N)
{
    int i = blockIdx.x * blockDim.x + threadIdx.x;
    if (i < n4)
        reinterpret_cast<float4*>(t)[i] = reinterpret_cast<const float4*>(feat)[i];
    if (i < N) deg[i] = 0.f;
}

__global__ void k_scatter(const float* __restrict__ feat, const int* __restrict__ ei,
                          float* __restrict__ t, float* __restrict__ deg, int E)
{
    int i = blockIdx.x * blockDim.x + threadIdx.x;
    if (i >= E * 20) return;
    int e = i / 20;
    int c = i - e * 20;
    int s = ei[e];
    int d = ei[E + e];
    float4 v = *reinterpret_cast<const float4*>(feat + (size_t)s * 80 + c * 4);
    float* p = t + (size_t)d * 80 + c * 4;
    asm volatile("red.global.add.v4.f32 [%0], {%1, %2, %3, %4};"
                 :: "l"(p), "f"(v.x), "f"(v.y), "f"(v.z), "f"(v.w) : "memory");
    if (c == 0) atomicAdd(deg + d, 1.f);
}

// ---------------- launch ----------------------------------------------------
static inline unsigned cdiv(long long a, long long b) { return (unsigned)((a + b - 1) / b); }

extern "C" void kernel_launch(void* const* d_in, const int* in_sizes, int n_in,
                              void* d_out, int out_size)
{
    const float* P    = (const float*)d_in[0];
    const int*   EI   = (const int*)  d_in[1];
    const float* W1   = (const float*)d_in[2];
    const float* b1   = (const float*)d_in[3];
    const float* W2   = (const float*)d_in[4];
    const float* b2   = (const float*)d_in[5];
    const float* W3   = (const float*)d_in[6];
    const float* b3   = (const float*)d_in[7];
    const float* W4   = (const float*)d_in[8];
    const float* b4   = (const float*)d_in[9];
    const float* Win  = (const float*)d_in[10];
    const float* bin_ = (const float*)d_in[11];
    const float* Wg1  = (const float*)d_in[12];
    const float* bg1  = (const float*)d_in[13];
    const float* Wg2  = (const float*)d_in[14];
    const float* bg2  = (const float*)d_in[15];
    const float* Wout = (const float*)d_in[16];
    const float* bout = (const float*)d_in[17];

    float* out  = (float*)d_out;
    float* mask = out;
    float* feat = out + (size_t)NN * 80;

    float *T, *DEG;
    __half *AC1, *AC2, *WC;
    cudaGetSymbolAddress((void**)&T,   g_t);
    cudaGetSymbolAddress((void**)&DEG, g_deg);
    cudaGetSymbolAddress((void**)&AC1, g_ac1);
    cudaGetSymbolAddress((void**)&AC2, g_ac2);
    cudaGetSymbolAddress((void**)&WC,  g_wc);

    // weight conv buffer offsets (elements)
    __half* W1c   = WC + 0;        // 1024 x 1536
    __half* W2c   = WC + 1572864;  // 1024 x 3072
    __half* W3c   = WC + 4718592;  // 512 x 3072
    __half* W4c   = WC + 6291456;  // 128 x 1536
    __half* Winc  = WC + 6488064;  // 512 x 384
    __half* Wg1c  = WC + 6684672;  // 512 x 1536
    __half* Wg2c  = WC + 7471104;  // 512 x 1536
    __half* Woutc = WC + 8257536;  // 128 x 1536

    const int M = NN;
    const int SMEM = 3 * 2 * 128 * 144;   // 110592 B -> 2 CTA/SM
    cudaFuncSetAttribute(gemm_mma<true,  true,  false, 1>, cudaFuncAttributeMaxDynamicSharedMemorySize, SMEM);
    cudaFuncSetAttribute(gemm_mma<false, true,  false, 1>, cudaFuncAttributeMaxDynamicSharedMemorySize, SMEM);
    cudaFuncSetAttribute(gemm_mma<false, true,  true,  1>, cudaFuncAttributeMaxDynamicSharedMemorySize, SMEM);
    cudaFuncSetAttribute(gemm_mma<false, false, false, 1>, cudaFuncAttributeMaxDynamicSharedMemorySize, SMEM);

    const dim3 blk(256);
    const unsigned rt = cdiv(M, 128);

    // --- all weight conversions (one kernel) ---
    WAll wa;
    wa.d[0] = { W1,   W1c,    512, 1024,  512, 1024 };
    wa.d[1] = { W2,   W2c,   1024, 1024, 1024, 1024 };
    wa.d[2] = { W3,   W3c,   1024,  512, 1024,  512 };
    wa.d[3] = { W4,   W4c,    512,   80,  512,  128 };
    wa.d[4] = { Win,  Winc,    80,  512,  128,  512 };
    wa.d[5] = { Wg1,  Wg1c,   512,  512,  512,  512 };
    wa.d[6] = { Wg2,  Wg2c,   512,  512,  512,  512 };
    wa.d[7] = { Wout, Woutc,  512,   80,  512,  128 };
    conv_wt_all<<<dim3(2048, 8), blk>>>(wa);

    // --- expand P to [hi|lo] ---
    conv_act<<<cdiv((long long)M * 128, 256), blk>>>(P, AC1, M, 512, 512);

    // --- aanet_proj: all SEC=1 (plain fp16) ---
    gemm_mma<true,  true,  false, 1><<<dim3(8, rt), blk, SMEM>>>(AC1, W1c, b1, nullptr, AC2, nullptr, M, 1024, 512);
    gemm_mma<true,  true,  false, 1><<<dim3(8, rt), blk, SMEM>>>(AC2, W2c, b2, nullptr, AC1, nullptr, M, 1024, 1024);
    gemm_mma<true,  true,  false, 1><<<dim3(4, rt), blk, SMEM>>>(AC1, W3c, b3, nullptr, AC2, nullptr, M, 512, 1024);
    gemm_mma<false, false, false, 1><<<dim3(1, rt), blk, SMEM>>>(AC2, W4c, b4, feat, nullptr, nullptr, M, 80, 512);

    // --- GIN aggregation in 80-dim feat space: t = feat + segsum(feat[src]) ---
    k_init_t<<<cdiv(NN * 20, 256), blk>>>(feat, T, DEG, NN * 20, NN);
    k_scatter<<<cdiv((long long)EE * 20, 256), blk>>>(feat, EI, T, DEG, EE);

    // --- g = t @ Win + (1 + deg) * bin  (deg fixup fused; SEC=1) ---
    conv_act<<<cdiv((long long)M * 32, 256), blk>>>(T, AC1, M, 80, 128);
    gemm_mma<false, true,  true,  1><<<dim3(4, rt), blk, SMEM>>>(AC1, Winc, bin_, nullptr, AC2, DEG, M, 512, 128);

    // --- GIN MLP: SEC=1 ---
    gemm_mma<true,  true,  false, 1><<<dim3(4, rt), blk, SMEM>>>(AC2, Wg1c, bg1, nullptr, AC1, nullptr, M, 512, 512);
    gemm_mma<false, true,  false, 1><<<dim3(4, rt), blk, SMEM>>>(AC1, Wg2c, bg2, nullptr, AC2, nullptr, M, 512, 512);

    // --- out_net: SEC=1 ---
    gemm_mma<false, false, false, 1><<<dim3(1, rt), blk, SMEM>>>(AC2, Woutc, bout, mask, nullptr, nullptr, M, 80, 512);
}

// round 16
// speedup vs baseline: 2.0549x; 1.0763x over previous
#include <cuda_runtime.h>
#include <cuda_fp16.h>
#include <cstdint>
#include <cstddef>

#define NN 50000
#define EE 800000

// ---------------- scratch (device globals: allocation-free) ----------------
__device__ __align__(256) __half g_ac1[(size_t)NN * 1024]; // fp16 act ping
__device__ __align__(256) __half g_ac2[(size_t)NN * 1024]; // fp16 act pong
__device__ __align__(256) float g_t  [(size_t)NN * 80];    // feat + agg
__device__ __align__(256) float g_deg[NN];
__device__ __align__(256) __half g_wc[2818048];            // fp16 weights (transposed)

// ---------------- warp-MMA helpers (baseline sm_80+ PTX only) --------------
__device__ __forceinline__ void ldsm4(uint32_t* r, uint32_t addr) {
    asm volatile("ldmatrix.sync.aligned.m8n8.x4.shared.b16 {%0,%1,%2,%3}, [%4];"
                 : "=r"(r[0]), "=r"(r[1]), "=r"(r[2]), "=r"(r[3]) : "r"(addr));
}
__device__ __forceinline__ void mma_fp16(float* c, const uint32_t* a,
                                         uint32_t b0, uint32_t b1) {
    asm volatile(
        "mma.sync.aligned.m16n8k16.row.col.f32.f16.f16.f32 "
        "{%0,%1,%2,%3}, {%4,%5,%6,%7}, {%8,%9}, {%0,%1,%2,%3};"
        : "+f"(c[0]), "+f"(c[1]), "+f"(c[2]), "+f"(c[3])
        : "r"(a[0]), "r"(a[1]), "r"(a[2]), "r"(a[3]), "r"(b0), "r"(b1));
}

// ---------------- fp16 tensor-core GEMM -------------------------------------
// A: [M, Kp] fp16 row-major.  Bw: [Np, Kp] fp16 (pre-transposed, padded).
// Plain fp16 x fp16 -> fp32 accum (weights+acts fp16-quantized, rel ~6.5e-4 total).
// CTA tile 128x128, warp tile 64x32, BK=64, 3-stage cp.async, 2 CTA/SM.
// SMEM rows: 128B data @ 144B pitch (odd 16B granules -> conflict-free ldsm).
// Inner loop: plain R8/R10 structure (ptxas schedules best; see R9/R11 PMs).
// Epilogue: X16 ? write fp16 (input of next GEMM) : write fp32.
// DEGFIX: +deg[r]*bias[c].
template <bool RELU, bool X16, bool DEGFIX>
__global__ void __launch_bounds__(256, 2)
gemm_mma(const __half* __restrict__ A, const __half* __restrict__ Bw,
         const float* __restrict__ bias, float* __restrict__ Cf,
         __half* __restrict__ Cx, const float* __restrict__ deg,
         int M, int Nreal, int Kp)
{
    constexpr int STAGES = 3;
    constexpr int PITCH  = 144;
    constexpr int TILEB  = 128 * PITCH;   // 18432
    constexpr int STAGEB = 2 * TILEB;

    extern __shared__ char smem[];
    const uint32_t sbase = (uint32_t)__cvta_generic_to_shared(smem);

    const int tid  = threadIdx.x;
    const int lane = tid & 31;
    const int wid  = tid >> 5;
    const int wm   = wid >> 2;            // 0..1
    const int wn   = wid & 3;             // 0..3
    const int block_row = blockIdx.y * 128;
    const int block_col = blockIdx.x * 128;

    const int KT  = Kp >> 6;              // chunks of 64
    const int ldA = Kp * 2;               // A row stride bytes
    const int ldB = Kp * 2;               // W row stride bytes
    const char* Ag = (const char*)A + (size_t)block_row * ldA;
    const char* Bg = (const char*)Bw + (size_t)block_col * ldB;

    // load mapping: row = tid/2, four 16B chunks at (tid&1)*64
    const int l_row = tid >> 1;
    const int l_c0  = (tid & 1) * 4;
    const int okA   = (block_row + l_row) < M ? 16 : 0;
    const char* ArowC = Ag + (size_t)((block_row + l_row) < M ? l_row : 0) * ldA;
    const char* BrowC = Bg + (size_t)l_row * ldB;

    auto load_stage = [&](int s, int kc) {
        uint32_t abuf = sbase + s * STAGEB + l_row * PITCH;
        uint32_t bbuf = abuf + TILEB;
        const char* Ak = ArowC + kc * 128;
        const char* Bk = BrowC + kc * 128;
#pragma unroll
        for (int it = 0; it < 4; it++) {
            int c = l_c0 + it;
            asm volatile("cp.async.cg.shared.global [%0], [%1], 16, %2;"
                         :: "r"(abuf + c * 16), "l"(Ak + c * 16), "r"(okA));
            asm volatile("cp.async.cg.shared.global [%0], [%1], 16;"
                         :: "r"(bbuf + c * 16), "l"(Bk + c * 16));
        }
    };

    float acc[4][4][4];
#pragma unroll
    for (int i = 0; i < 4; i++)
#pragma unroll
        for (int j = 0; j < 4; j++)
#pragma unroll
            for (int k = 0; k < 4; k++) acc[i][j][k] = 0.f;

    load_stage(0, 0);
    asm volatile("cp.async.commit_group;" ::: "memory");
    if (KT > 1) load_stage(1, 1);
    asm volatile("cp.async.commit_group;" ::: "memory");

    const uint32_t lrow = lane & 15;
    const uint32_t lhi  = (lane >> 4) << 4;
    uint32_t aoff[4], boff[2];
#pragma unroll
    for (int mt = 0; mt < 4; mt++)
        aoff[mt] = (wm * 64 + mt * 16 + lrow) * PITCH + lhi;
#pragma unroll
    for (int nt = 0; nt < 2; nt++)
        boff[nt] = TILEB + (wn * 32 + nt * 16 + lrow) * PITCH + lhi;

    int slot = 0;
    for (int ks = 0; ks < KT; ks++) {
        asm volatile("cp.async.wait_group 1;" ::: "memory");
        __syncthreads();
        int kn = ks + STAGES - 1;
        int nslot = slot + 1 == STAGES ? 0 : slot + 1;
        int lslot = nslot + 1 == STAGES ? 0 : nslot + 1;
        if (kn < KT) load_stage(lslot, kn);
        asm volatile("cp.async.commit_group;" ::: "memory");

        uint32_t buf = sbase + slot * STAGEB;
#pragma unroll
        for (int kk = 0; kk < 4; kk++) {          // four k16 steps per chunk
            uint32_t col = kk * 32;
            uint32_t afr[4][4];
#pragma unroll
            for (int mt = 0; mt < 4; mt++)
                ldsm4(afr[mt], buf + aoff[mt] + col);
            uint32_t bq[2][4];
#pragma unroll
            for (int nt = 0; nt < 2; nt++)
                ldsm4(bq[nt], buf + boff[nt] + col);
#pragma unroll
            for (int mt = 0; mt < 4; mt++)
#pragma unroll
                for (int n8 = 0; n8 < 4; n8++)
                    mma_fp16(acc[mt][n8], afr[mt],
                             bq[n8 >> 1][n8 & 1], bq[n8 >> 1][(n8 & 1) + 2]);
        }
        slot = nslot;
    }

    // epilogue
    const int g = lane >> 2, t = lane & 3;
#pragma unroll
    for (int mt = 0; mt < 4; mt++) {
#pragma unroll
        for (int n8 = 0; n8 < 4; n8++) {
            int c = block_col + wn * 32 + n8 * 8 + t * 2;
            if (c >= Nreal) continue;
            float bx = __ldg(bias + c), by = __ldg(bias + c + 1);
#pragma unroll
            for (int h = 0; h < 2; h++) {
                int r = block_row + wm * 64 + mt * 16 + g + h * 8;
                if (r >= M) continue;
                float vx = acc[mt][n8][h * 2 + 0] + bx;
                float vy = acc[mt][n8][h * 2 + 1] + by;
                if (DEGFIX) {
                    float dg = __ldg(deg + r);
                    vx += dg * bx;
                    vy += dg * by;
                }
                if (RELU) { vx = fmaxf(vx, 0.f); vy = fmaxf(vy, 0.f); }
                if (X16) {
                    __half2 hv;
                    hv.x = __float2half_rn(vx);
                    hv.y = __float2half_rn(vy);
                    *reinterpret_cast<__half2*>(Cx + (size_t)r * Nreal + c) = hv;
                } else {
                    float2 v; v.x = vx; v.y = vy;
                    *reinterpret_cast<float2*>(Cf + (size_t)r * Nreal + c) = v;
                }
            }
        }
    }
}

// ---------------- fp32 -> fp16 conversion (float4 in, half2 out) ------------
__global__ void conv_act(const float* __restrict__ in, __half* __restrict__ out,
                         int M, int K, int Kp)
{
    int q = Kp >> 2;
    int idx = blockIdx.x * blockDim.x + threadIdx.x;
    if (idx >= M * q) return;
    int r = idx / q;
    int k4 = (idx - r * q) * 4;
    float4 x = make_float4(0.f, 0.f, 0.f, 0.f);
    if (k4 < K)
        x = *reinterpret_cast<const float4*>(in + (size_t)r * K + k4);
    __half2 h0, h1;
    h0.x = __float2half_rn(x.x); h0.y = __float2half_rn(x.y);
    h1.x = __float2half_rn(x.z); h1.y = __float2half_rn(x.w);
    __half* b = out + (size_t)r * Kp;
    reinterpret_cast<__half2*>(b + k4)[0] = h0;
    reinterpret_cast<__half2*>(b + k4)[1] = h1;
}

// ---------------- all weight conversions in ONE kernel ----------------------
// W[K,N] fp32 -> Wt[Np, Kp] fp16 (transposed + zero-padded)
struct WDesc { const float* W; __half* out; int K, N, Kp, Np; };
struct WAll  { WDesc d[8]; };

__global__ void conv_wt_all(WAll wa)
{
    WDesc d = wa.d[blockIdx.y];
    int tot = d.Np * d.Kp;
    for (int idx = blockIdx.x * blockDim.x + threadIdx.x; idx < tot;
         idx += gridDim.x * blockDim.x) {
        int n = idx / d.Kp;
        int k = idx - n * d.Kp;
        float x = (k < d.K && n < d.N) ? d.W[(size_t)k * d.N + n] : 0.f;
        d.out[(size_t)n * d.Kp + k] = __float2half_rn(x);
    }
}

// ---------------- GIN aggregation on 80-dim feat ----------------------------
__global__ void k_init_t(const float* __restrict__ feat, float* __restrict__ t,
                         float* __restrict__ deg, int n4, int N)
{
    int i = blockIdx.x * blockDim.x + threadIdx.x;
    if (i < n4)
        reinterpret_cast<float4*>(t)[i] = reinterpret_cast<const float4*>(feat)[i];
    if (i < N) deg[i] = 0.f;
}

__global__ void k_scatter(const float* __restrict__ feat, const int* __restrict__ ei,
                          float* __restrict__ t, float* __restrict__ deg, int E)
{
    int i = blockIdx.x * blockDim.x + threadIdx.x;
    if (i >= E * 20) return;
    int e = i / 20;
    int c = i - e * 20;
    int s = ei[e];
    int d = ei[E + e];
    float4 v = *reinterpret_cast<const float4*>(feat + (size_t)s * 80 + c * 4);
    float* p = t + (size_t)d * 80 + c * 4;
    asm volatile("red.global.add.v4.f32 [%0], {%1, %2, %3, %4};"
                 :: "l"(p), "f"(v.x), "f"(v.y), "f"(v.z), "f"(v.w) : "memory");
    if (c == 0) atomicAdd(deg + d, 1.f);
}

// ---------------- launch ----------------------------------------------------
static inline unsigned cdiv(long long a, long long b) { return (unsigned)((a + b - 1) / b); }

extern "C" void kernel_launch(void* const* d_in, const int* in_sizes, int n_in,
                              void* d_out, int out_size)
{
    const float* P    = (const float*)d_in[0];
    const int*   EI   = (const int*)  d_in[1];
    const float* W1   = (const float*)d_in[2];
    const float* b1   = (const float*)d_in[3];
    const float* W2   = (const float*)d_in[4];
    const float* b2   = (const float*)d_in[5];
    const float* W3   = (const float*)d_in[6];
    const float* b3   = (const float*)d_in[7];
    const float* W4   = (const float*)d_in[8];
    const float* b4   = (const float*)d_in[9];
    const float* Win  = (const float*)d_in[10];
    const float* bin_ = (const float*)d_in[11];
    const float* Wg1  = (const float*)d_in[12];
    const float* bg1  = (const float*)d_in[13];
    const float* Wg2  = (const float*)d_in[14];
    const float* bg2  = (const float*)d_in[15];
    const float* Wout = (const float*)d_in[16];
    const float* bout = (const float*)d_in[17];

    float* out  = (float*)d_out;
    float* mask = out;
    float* feat = out + (size_t)NN * 80;

    float *T, *DEG;
    __half *AC1, *AC2, *WC;
    cudaGetSymbolAddress((void**)&T,   g_t);
    cudaGetSymbolAddress((void**)&DEG, g_deg);
    cudaGetSymbolAddress((void**)&AC1, g_ac1);
    cudaGetSymbolAddress((void**)&AC2, g_ac2);
    cudaGetSymbolAddress((void**)&WC,  g_wc);

    // weight conv buffer offsets (elements, single-section [Np, Kp])
    __half* W1c   = WC + 0;        // 1024 x 512
    __half* W2c   = WC + 524288;   // 1024 x 1024
    __half* W3c   = WC + 1572864;  // 512 x 1024
    __half* W4c   = WC + 2097152;  // 128 x 512
    __half* Winc  = WC + 2162688;  // 512 x 128
    __half* Wg1c  = WC + 2228224;  // 512 x 512
    __half* Wg2c  = WC + 2490368;  // 512 x 512
    __half* Woutc = WC + 2752512;  // 128 x 512

    const int M = NN;
    const int SMEM = 3 * 2 * 128 * 144;   // 110592 B -> 2 CTA/SM
    cudaFuncSetAttribute(gemm_mma<true,  true,  false>, cudaFuncAttributeMaxDynamicSharedMemorySize, SMEM);
    cudaFuncSetAttribute(gemm_mma<false, true,  false>, cudaFuncAttributeMaxDynamicSharedMemorySize, SMEM);
    cudaFuncSetAttribute(gemm_mma<false, true,  true >, cudaFuncAttributeMaxDynamicSharedMemorySize, SMEM);
    cudaFuncSetAttribute(gemm_mma<false, false, false>, cudaFuncAttributeMaxDynamicSharedMemorySize, SMEM);

    const dim3 blk(256);
    const unsigned rt = cdiv(M, 128);

    // --- all weight conversions (one kernel) ---
    WAll wa;
    wa.d[0] = { W1,   W1c,    512, 1024,  512, 1024 };
    wa.d[1] = { W2,   W2c,   1024, 1024, 1024, 1024 };
    wa.d[2] = { W3,   W3c,   1024,  512, 1024,  512 };
    wa.d[3] = { W4,   W4c,    512,   80,  512,  128 };
    wa.d[4] = { Win,  Winc,    80,  512,  128,  512 };
    wa.d[5] = { Wg1,  Wg1c,   512,  512,  512,  512 };
    wa.d[6] = { Wg2,  Wg2c,   512,  512,  512,  512 };
    wa.d[7] = { Wout, Woutc,  512,   80,  512,  128 };
    conv_wt_all<<<dim3(1024, 8), blk>>>(wa);

    // --- convert P to fp16 ---
    conv_act<<<cdiv((long long)M * 128, 256), blk>>>(P, AC1, M, 512, 512);

    // --- aanet_proj (plain fp16) ---
    gemm_mma<true,  true,  false><<<dim3(8, rt), blk, SMEM>>>(AC1, W1c, b1, nullptr, AC2, nullptr, M, 1024, 512);
    gemm_mma<true,  true,  false><<<dim3(8, rt), blk, SMEM>>>(AC2, W2c, b2, nullptr, AC1, nullptr, M, 1024, 1024);
    gemm_mma<true,  true,  false><<<dim3(4, rt), blk, SMEM>>>(AC1, W3c, b3, nullptr, AC2, nullptr, M, 512, 1024);
    gemm_mma<false, false, false><<<dim3(1, rt), blk, SMEM>>>(AC2, W4c, b4, feat, nullptr, nullptr, M, 80, 512);

    // --- GIN aggregation in 80-dim feat space: t = feat + segsum(feat[src]) ---
    k_init_t<<<cdiv(NN * 20, 256), blk>>>(feat, T, DEG, NN * 20, NN);
    k_scatter<<<cdiv((long long)EE * 20, 256), blk>>>(feat, EI, T, DEG, EE);

    // --- g = t @ Win + (1 + deg) * bin  (deg fixup fused) ---
    conv_act<<<cdiv((long long)M * 32, 256), blk>>>(T, AC1, M, 80, 128);
    gemm_mma<false, true,  true ><<<dim3(4, rt), blk, SMEM>>>(AC1, Winc, bin_, nullptr, AC2, DEG, M, 512, 128);

    // --- GIN MLP ---
    gemm_mma<true,  true,  false><<<dim3(4, rt), blk, SMEM>>>(AC2, Wg1c, bg1, nullptr, AC1, nullptr, M, 512, 512);
    gemm_mma<false, true,  false><<<dim3(4, rt), blk, SMEM>>>(AC1, Wg2c, bg2, nullptr, AC2, nullptr, M, 512, 512);

    // --- out_net ---
    gemm_mma<false, false, false><<<dim3(1, rt), blk, SMEM>>>(AC2, Woutc, bout, mask, nullptr, nullptr, M, 80, 512);
}

// round 17
// speedup vs baseline: 2.1792x; 1.0605x over previous
#include <cuda_runtime.h>
#include <cuda_fp16.h>
#include <cstdint>
#include <cstddef>

#define NN 50000
#define EE 800000

// ---------------- scratch (device globals: allocation-free) ----------------
__device__ __align__(256) __half g_ac1[(size_t)NN * 1024]; // fp16 act ping
__device__ __align__(256) __half g_ac2[(size_t)NN * 1024]; // fp16 act pong
__device__ __align__(256) float g_t  [(size_t)NN * 80];    // feat + agg
__device__ __align__(256) float g_deg[NN];
__device__ __align__(256) __half g_wc[2818048];            // fp16 weights (transposed)
__device__ __align__(256) float g_bc[128];                 // combined bias

// ---------------- warp-MMA helpers (baseline sm_80+ PTX only) --------------
__device__ __forceinline__ void ldsm4(uint32_t* r, uint32_t addr) {
    asm volatile("ldmatrix.sync.aligned.m8n8.x4.shared.b16 {%0,%1,%2,%3}, [%4];"
                 : "=r"(r[0]), "=r"(r[1]), "=r"(r[2]), "=r"(r[3]) : "r"(addr));
}
__device__ __forceinline__ void mma_fp16(float* c, const uint32_t* a,
                                         uint32_t b0, uint32_t b1) {
    asm volatile(
        "mma.sync.aligned.m16n8k16.row.col.f32.f16.f16.f32 "
        "{%0,%1,%2,%3}, {%4,%5,%6,%7}, {%8,%9}, {%0,%1,%2,%3};"
        : "+f"(c[0]), "+f"(c[1]), "+f"(c[2]), "+f"(c[3])
        : "r"(a[0]), "r"(a[1]), "r"(a[2]), "r"(a[3]), "r"(b0), "r"(b1));
}

// ---------------- fp16 tensor-core GEMM -------------------------------------
// A: [M, Kp] fp16 row-major.  Bw: [Np, Kp] fp16 (pre-transposed, padded).
// Plain fp16 x fp16 -> fp32 accum.
// CTA tile 128x128, warp tile 64x32, BK=64, 3-stage cp.async, 2 CTA/SM.
// SMEM rows: 128B data @ 144B pitch (odd 16B granules -> conflict-free ldsm).
// Inner loop: plain R8/R10 structure (ptxas schedules best; see R9/R11 PMs).
// Epilogue: X16 ? write fp16 (input of next GEMM) : write fp32.
// DEGFIX: +deg[r]*bias[c].
template <bool RELU, bool X16, bool DEGFIX>
__global__ void __launch_bounds__(256, 2)
gemm_mma(const __half* __restrict__ A, const __half* __restrict__ Bw,
         const float* __restrict__ bias, float* __restrict__ Cf,
         __half* __restrict__ Cx, const float* __restrict__ deg,
         int M, int Nreal, int Kp)
{
    constexpr int STAGES = 3;
    constexpr int PITCH  = 144;
    constexpr int TILEB  = 128 * PITCH;   // 18432
    constexpr int STAGEB = 2 * TILEB;

    extern __shared__ char smem[];
    const uint32_t sbase = (uint32_t)__cvta_generic_to_shared(smem);

    const int tid  = threadIdx.x;
    const int lane = tid & 31;
    const int wid  = tid >> 5;
    const int wm   = wid >> 2;            // 0..1
    const int wn   = wid & 3;             // 0..3
    const int block_row = blockIdx.y * 128;
    const int block_col = blockIdx.x * 128;

    const int KT  = Kp >> 6;              // chunks of 64
    const int ldA = Kp * 2;               // A row stride bytes
    const int ldB = Kp * 2;               // W row stride bytes
    const char* Ag = (const char*)A + (size_t)block_row * ldA;
    const char* Bg = (const char*)Bw + (size_t)block_col * ldB;

    // load mapping: row = tid/2, four 16B chunks at (tid&1)*64
    const int l_row = tid >> 1;
    const int l_c0  = (tid & 1) * 4;
    const int okA   = (block_row + l_row) < M ? 16 : 0;
    const char* ArowC = Ag + (size_t)((block_row + l_row) < M ? l_row : 0) * ldA;
    const char* BrowC = Bg + (size_t)l_row * ldB;

    auto load_stage = [&](int s, int kc) {
        uint32_t abuf = sbase + s * STAGEB + l_row * PITCH;
        uint32_t bbuf = abuf + TILEB;
        const char* Ak = ArowC + kc * 128;
        const char* Bk = BrowC + kc * 128;
#pragma unroll
        for (int it = 0; it < 4; it++) {
            int c = l_c0 + it;
            asm volatile("cp.async.cg.shared.global [%0], [%1], 16, %2;"
                         :: "r"(abuf + c * 16), "l"(Ak + c * 16), "r"(okA));
            asm volatile("cp.async.cg.shared.global [%0], [%1], 16;"
                         :: "r"(bbuf + c * 16), "l"(Bk + c * 16));
        }
    };

    float acc[4][4][4];
#pragma unroll
    for (int i = 0; i < 4; i++)
#pragma unroll
        for (int j = 0; j < 4; j++)
#pragma unroll
            for (int k = 0; k < 4; k++) acc[i][j][k] = 0.f;

    load_stage(0, 0);
    asm volatile("cp.async.commit_group;" ::: "memory");
    if (KT > 1) load_stage(1, 1);
    asm volatile("cp.async.commit_group;" ::: "memory");

    const uint32_t lrow = lane & 15;
    const uint32_t lhi  = (lane >> 4) << 4;
    uint32_t aoff[4], boff[2];
#pragma unroll
    for (int mt = 0; mt < 4; mt++)
        aoff[mt] = (wm * 64 + mt * 16 + lrow) * PITCH + lhi;
#pragma unroll
    for (int nt = 0; nt < 2; nt++)
        boff[nt] = TILEB + (wn * 32 + nt * 16 + lrow) * PITCH + lhi;

    int slot = 0;
    for (int ks = 0; ks < KT; ks++) {
        asm volatile("cp.async.wait_group 1;" ::: "memory");
        __syncthreads();
        int kn = ks + STAGES - 1;
        int nslot = slot + 1 == STAGES ? 0 : slot + 1;
        int lslot = nslot + 1 == STAGES ? 0 : nslot + 1;
        if (kn < KT) load_stage(lslot, kn);
        asm volatile("cp.async.commit_group;" ::: "memory");

        uint32_t buf = sbase + slot * STAGEB;
#pragma unroll
        for (int kk = 0; kk < 4; kk++) {          // four k16 steps per chunk
            uint32_t col = kk * 32;
            uint32_t afr[4][4];
#pragma unroll
            for (int mt = 0; mt < 4; mt++)
                ldsm4(afr[mt], buf + aoff[mt] + col);
            uint32_t bq[2][4];
#pragma unroll
            for (int nt = 0; nt < 2; nt++)
                ldsm4(bq[nt], buf + boff[nt] + col);
#pragma unroll
            for (int mt = 0; mt < 4; mt++)
#pragma unroll
                for (int n8 = 0; n8 < 4; n8++)
                    mma_fp16(acc[mt][n8], afr[mt],
                             bq[n8 >> 1][n8 & 1], bq[n8 >> 1][(n8 & 1) + 2]);
        }
        slot = nslot;
    }

    // epilogue
    const int g = lane >> 2, t = lane & 3;
#pragma unroll
    for (int mt = 0; mt < 4; mt++) {
#pragma unroll
        for (int n8 = 0; n8 < 4; n8++) {
            int c = block_col + wn * 32 + n8 * 8 + t * 2;
            if (c >= Nreal) continue;
            float bx = __ldg(bias + c), by = __ldg(bias + c + 1);
#pragma unroll
            for (int h = 0; h < 2; h++) {
                int r = block_row + wm * 64 + mt * 16 + g + h * 8;
                if (r >= M) continue;
                float vx = acc[mt][n8][h * 2 + 0] + bx;
                float vy = acc[mt][n8][h * 2 + 1] + by;
                if (DEGFIX) {
                    float dg = __ldg(deg + r);
                    vx += dg * bx;
                    vy += dg * by;
                }
                if (RELU) { vx = fmaxf(vx, 0.f); vy = fmaxf(vy, 0.f); }
                if (X16) {
                    __half2 hv;
                    hv.x = __float2half_rn(vx);
                    hv.y = __float2half_rn(vy);
                    *reinterpret_cast<__half2*>(Cx + (size_t)r * Nreal + c) = hv;
                } else {
                    float2 v; v.x = vx; v.y = vy;
                    *reinterpret_cast<float2*>(Cf + (size_t)r * Nreal + c) = v;
                }
            }
        }
    }
}

// ---------------- fp32 -> fp16 conversion (float4 in, half2 out) ------------
__global__ void conv_act(const float* __restrict__ in, __half* __restrict__ out,
                         int M, int K, int Kp)
{
    int q = Kp >> 2;
    int idx = blockIdx.x * blockDim.x + threadIdx.x;
    if (idx >= M * q) return;
    int r = idx / q;
    int k4 = (idx - r * q) * 4;
    float4 x = make_float4(0.f, 0.f, 0.f, 0.f);
    if (k4 < K)
        x = *reinterpret_cast<const float4*>(in + (size_t)r * K + k4);
    __half2 h0, h1;
    h0.x = __float2half_rn(x.x); h0.y = __float2half_rn(x.y);
    h1.x = __float2half_rn(x.z); h1.y = __float2half_rn(x.w);
    __half* b = out + (size_t)r * Kp;
    reinterpret_cast<__half2*>(b + k4)[0] = h0;
    reinterpret_cast<__half2*>(b + k4)[1] = h1;
}

// ---------------- weight conversions (6 weights) ----------------------------
// W[K,N] fp32 -> Wt[Np, Kp] fp16 (transposed + zero-padded)
struct WDesc { const float* W; __half* out; int K, N, Kp, Np; };
struct WAll  { WDesc d[6]; };

__global__ void conv_wt_all(WAll wa)
{
    WDesc d = wa.d[blockIdx.y];
    int tot = d.Np * d.Kp;
    for (int idx = blockIdx.x * blockDim.x + threadIdx.x; idx < tot;
         idx += gridDim.x * blockDim.x) {
        int n = idx / d.Kp;
        int k = idx - n * d.Kp;
        float x = (k < d.K && n < d.N) ? d.W[(size_t)k * d.N + n] : 0.f;
        d.out[(size_t)n * d.Kp + k] = __float2half_rn(x);
    }
}

// ---------------- Wg2 @ Wout fusion -----------------------------------------
// Wc[n][k] = sum_j Wg2[k][j] * Wout[j][n]   (combined [512 -> 80], transposed
// layout [Np=128][Kp=512] fp16).  bc[n] = bout[n] + sum_j bg2[j]*Wout[j][n].
// Product computed in fp32, quantized once -> replaces two fp16 layers.
__global__ void combine_wout(const float* __restrict__ Wg2,
                             const float* __restrict__ Wout,
                             const float* __restrict__ bg2,
                             const float* __restrict__ bout,
                             __half* __restrict__ Wc, float* __restrict__ bc)
{
    int idx = blockIdx.x * blockDim.x + threadIdx.x;   // 128*512
    if (idx >= 128 * 512) return;
    int n = idx & 127;          // consecutive threads -> coalesced Wout reads
    int k = idx >> 7;
    float s = 0.f;
    if (n < 80) {
        for (int j = 0; j < 512; j++)
            s += Wg2[(size_t)k * 512 + j] * __ldg(Wout + (size_t)j * 80 + n);
    }
    Wc[(size_t)n * 512 + k] = __float2half_rn(s);
    if (k == 0) {
        if (n < 80) {
            float b = bout[n];
            for (int j = 0; j < 512; j++)
                b += bg2[j] * __ldg(Wout + (size_t)j * 80 + n);
            bc[n] = b;
        } else {
            bc[n] = 0.f;
        }
    }
}

// ---------------- GIN aggregation on 80-dim feat ----------------------------
__global__ void k_init_t(const float* __restrict__ feat, float* __restrict__ t,
                         float* __restrict__ deg, int n4, int N)
{
    int i = blockIdx.x * blockDim.x + threadIdx.x;
    if (i < n4)
        reinterpret_cast<float4*>(t)[i] = reinterpret_cast<const float4*>(feat)[i];
    if (i < N) deg[i] = 0.f;
}

__global__ void k_scatter(const float* __restrict__ feat, const int* __restrict__ ei,
                          float* __restrict__ t, float* __restrict__ deg, int E)
{
    int i = blockIdx.x * blockDim.x + threadIdx.x;
    if (i >= E * 20) return;
    int e = i / 20;
    int c = i - e * 20;
    int s = ei[e];
    int d = ei[E + e];
    float4 v = *reinterpret_cast<const float4*>(feat + (size_t)s * 80 + c * 4);
    float* p = t + (size_t)d * 80 + c * 4;
    asm volatile("red.global.add.v4.f32 [%0], {%1, %2, %3, %4};"
                 :: "l"(p), "f"(v.x), "f"(v.y), "f"(v.z), "f"(v.w) : "memory");
    if (c == 0) atomicAdd(deg + d, 1.f);
}

// ---------------- launch ----------------------------------------------------
static inline unsigned cdiv(long long a, long long b) { return (unsigned)((a + b - 1) / b); }

extern "C" void kernel_launch(void* const* d_in, const int* in_sizes, int n_in,
                              void* d_out, int out_size)
{
    const float* P    = (const float*)d_in[0];
    const int*   EI   = (const int*)  d_in[1];
    const float* W1   = (const float*)d_in[2];
    const float* b1   = (const float*)d_in[3];
    const float* W2   = (const float*)d_in[4];
    const float* b2   = (const float*)d_in[5];
    const float* W3   = (const float*)d_in[6];
    const float* b3   = (const float*)d_in[7];
    const float* W4   = (const float*)d_in[8];
    const float* b4   = (const float*)d_in[9];
    const float* Win  = (const float*)d_in[10];
    const float* bin_ = (const float*)d_in[11];
    const float* Wg1  = (const float*)d_in[12];
    const float* bg1  = (const float*)d_in[13];
    const float* Wg2  = (const float*)d_in[14];
    const float* bg2  = (const float*)d_in[15];
    const float* Wout = (const float*)d_in[16];
    const float* bout = (const float*)d_in[17];

    float* out  = (float*)d_out;
    float* mask = out;
    float* feat = out + (size_t)NN * 80;

    float *T, *DEG, *BC;
    __half *AC1, *AC2, *WC;
    cudaGetSymbolAddress((void**)&T,   g_t);
    cudaGetSymbolAddress((void**)&DEG, g_deg);
    cudaGetSymbolAddress((void**)&AC1, g_ac1);
    cudaGetSymbolAddress((void**)&AC2, g_ac2);
    cudaGetSymbolAddress((void**)&WC,  g_wc);
    cudaGetSymbolAddress((void**)&BC,  g_bc);

    // weight conv buffer offsets (elements, single-section [Np, Kp])
    __half* W1c   = WC + 0;        // 1024 x 512
    __half* W2c   = WC + 524288;   // 1024 x 1024
    __half* W3c   = WC + 1572864;  // 512 x 1024
    __half* W4c   = WC + 2097152;  // 128 x 512
    __half* Winc  = WC + 2162688;  // 512 x 128
    __half* Wg1c  = WC + 2228224;  // 512 x 512
    __half* Wcomb = WC + 2490368;  // 128 x 512 (Wg2@Wout combined)

    const int M = NN;
    const int SMEM = 3 * 2 * 128 * 144;   // 110592 B -> 2 CTA/SM
    cudaFuncSetAttribute(gemm_mma<true,  true,  false>, cudaFuncAttributeMaxDynamicSharedMemorySize, SMEM);
    cudaFuncSetAttribute(gemm_mma<false, true,  false>, cudaFuncAttributeMaxDynamicSharedMemorySize, SMEM);
    cudaFuncSetAttribute(gemm_mma<false, true,  true >, cudaFuncAttributeMaxDynamicSharedMemorySize, SMEM);
    cudaFuncSetAttribute(gemm_mma<false, false, false>, cudaFuncAttributeMaxDynamicSharedMemorySize, SMEM);

    const dim3 blk(256);
    const unsigned rt = cdiv(M, 128);

    // --- weight conversions (6 plain) + Wg2@Wout fusion ---
    WAll wa;
    wa.d[0] = { W1,   W1c,    512, 1024,  512, 1024 };
    wa.d[1] = { W2,   W2c,   1024, 1024, 1024, 1024 };
    wa.d[2] = { W3,   W3c,   1024,  512, 1024,  512 };
    wa.d[3] = { W4,   W4c,    512,   80,  512,  128 };
    wa.d[4] = { Win,  Winc,    80,  512,  128,  512 };
    wa.d[5] = { Wg1,  Wg1c,   512,  512,  512,  512 };
    conv_wt_all<<<dim3(1024, 6), blk>>>(wa);
    combine_wout<<<cdiv(128 * 512, 256), blk>>>(Wg2, Wout, bg2, bout, Wcomb, BC);

    // --- convert P to fp16 ---
    conv_act<<<cdiv((long long)M * 128, 256), blk>>>(P, AC1, M, 512, 512);

    // --- aanet_proj (plain fp16) ---
    gemm_mma<true,  true,  false><<<dim3(8, rt), blk, SMEM>>>(AC1, W1c, b1, nullptr, AC2, nullptr, M, 1024, 512);
    gemm_mma<true,  true,  false><<<dim3(8, rt), blk, SMEM>>>(AC2, W2c, b2, nullptr, AC1, nullptr, M, 1024, 1024);
    gemm_mma<true,  true,  false><<<dim3(4, rt), blk, SMEM>>>(AC1, W3c, b3, nullptr, AC2, nullptr, M, 512, 1024);
    gemm_mma<false, false, false><<<dim3(1, rt), blk, SMEM>>>(AC2, W4c, b4, feat, nullptr, nullptr, M, 80, 512);

    // --- GIN aggregation in 80-dim feat space: t = feat + segsum(feat[src]) ---
    k_init_t<<<cdiv(NN * 20, 256), blk>>>(feat, T, DEG, NN * 20, NN);
    k_scatter<<<cdiv((long long)EE * 20, 256), blk>>>(feat, EI, T, DEG, EE);

    // --- g = t @ Win + (1 + deg) * bin  (deg fixup fused) ---
    conv_act<<<cdiv((long long)M * 32, 256), blk>>>(T, AC1, M, 80, 128);
    gemm_mma<false, true,  true ><<<dim3(4, rt), blk, SMEM>>>(AC1, Winc, bin_, nullptr, AC2, DEG, M, 512, 128);

    // --- GIN MLP layer 1 ---
    gemm_mma<true,  true,  false><<<dim3(4, rt), blk, SMEM>>>(AC2, Wg1c, bg1, nullptr, AC1, nullptr, M, 512, 512);

    // --- fused (Wg2 @ Wout): mask = relu_out @ Wcomb + bc ---
    gemm_mma<false, false, false><<<dim3(1, rt), blk, SMEM>>>(AC1, Wcomb, BC, mask, nullptr, nullptr, M, 80, 512);
}